// round 9
// baseline (speedup 1.0000x reference)
#include <cuda_runtime.h>
#include <cuda_fp16.h>
#include <math.h>
#include <stdint.h>

#define B_   64
#define N_   36
#define ROWS 2304      // B_*N_
#define DF   2048
#define DATT 512

// packed chunk sizes (32-bit words)
#define PA_W 3072      // 128 rows x 24 words (16 half2 + 8 pad)
#define PB_W 4160      // 16 word-rows x 260
#define PR_F 1440      // 36 x 40 floats (raw fp32 relattn operands)

// ---------------- scratch ----------------------------------------------------
__device__ float    g_tmp1[ROWS * DF];
__device__ float    g_tmp2[ROWS * DF];
__device__ float    g_ra[ROWS * DF];
__device__ float    g_rb[ROWS * DF];
__device__ float    g_ba[ROWS * DF];
__device__ float    g_bb[ROWS * DF];
__device__ uint32_t g_pqe[18 * 64 * PA_W];    // packed fp16 A operands
__device__ uint32_t g_pobj[18 * 64 * PA_W];
__device__ uint32_t g_pfus[18 * 64 * PA_W];
__device__ uint32_t g_pWq[8 * 64 * PB_W];     // packed fp16 weights
__device__ uint32_t g_pWo[8 * 64 * PB_W];
__device__ uint32_t g_pWfa[8 * 64 * PB_W];
__device__ uint32_t g_pWfb[8 * 64 * PB_W];
__device__ uint32_t g_pW0[2 * 64 * PB_W];
__device__ float    g_pra[B_ * 64 * PR_F];    // packed RAW fp32 relattn operands
__device__ float    g_prb[B_ * 64 * PR_F];
__device__ float    g_pba[B_ * 64 * PR_F];
__device__ float    g_pbb[B_ * 64 * PR_F];
__device__ float    g_scp[2 * 9 * B_ * 144];
__device__ float    g_attb[ROWS * N_];

// ---------------- PTX helpers ------------------------------------------------
__device__ __forceinline__ uint32_t smem_u32(const void* p) {
    uint32_t a;
    asm("{ .reg .u64 t; cvta.to.shared.u64 t, %1; cvt.u32.u64 %0, t; }" : "=r"(a) : "l"(p));
    return a;
}
__device__ __forceinline__ uint32_t packh2(float x, float y) {
    __half2 h = __floats2half2_rn(x, y);
    return *(uint32_t*)&h;
}
// fp16 m16n8k16, fp32 accumulate
__device__ __forceinline__ void mma16(float* d, const uint32_t* a, const uint32_t* b) {
    asm volatile("mma.sync.aligned.m16n8k16.row.col.f32.f16.f16.f32 "
                 "{%0,%1,%2,%3}, {%4,%5,%6,%7}, {%8,%9}, {%0,%1,%2,%3};"
                 : "+f"(d[0]), "+f"(d[1]), "+f"(d[2]), "+f"(d[3])
                 : "r"(a[0]), "r"(a[1]), "r"(a[2]), "r"(a[3]),
                   "r"(b[0]), "r"(b[1]));
}
__device__ __forceinline__ void blkcp(uint32_t dst, const void* src,
                                      uint32_t bytes, uint32_t bar) {
    asm volatile("cp.async.bulk.shared::cta.global.mbarrier::complete_tx::bytes "
                 "[%0], [%1], %2, [%3];"
                 :: "r"(dst), "l"(src), "r"(bytes), "r"(bar) : "memory");
}
#define MBAR_INIT(a, n) \
    asm volatile("mbarrier.init.shared.b64 [%0], %1;" :: "r"(a), "r"(n) : "memory")
#define MBAR_EXPECT(a, n) \
    asm volatile("mbarrier.arrive.expect_tx.shared.b64 _, [%0], %1;" :: "r"(a), "r"(n) : "memory")
#define MBAR_WAIT(a, ph) do {                                                   \
    uint32_t _m = (a), _p = (ph), _d;                                           \
    asm volatile("{\n\t.reg .pred p;\n\t"                                       \
        "mbarrier.try_wait.parity.acquire.cta.shared::cta.b64 p, [%1], %2;\n\t" \
        "selp.b32 %0, 1, 0, p;\n\t}" : "=r"(_d) : "r"(_m), "r"(_p) : "memory"); \
    if (!_d) {                                                                  \
        asm volatile("{\n\t.reg .pred P;\n\t"                                   \
            "WL_%=:\n\t"                                                        \
            "mbarrier.try_wait.parity.acquire.cta.shared::cta.b64 P, [%0], %1, 0x989680;\n\t" \
            "@P bra.uni WD_%=;\n\t"                                             \
            "bra.uni WL_%=;\n\t"                                                \
            "WD_%=:\n\t}" :: "r"(_m), "r"(_p) : "memory");                      \
    } } while (0)

// k-word permutation within a K=16 block (8 half2 words):
// logical w (k=2w,2w+1) -> phys (w<4 ? 2w : 2(w-4)+1), so fragment pairs
// (w=c, w=4+c) are adjacent -> LDS.64 for A.
__device__ __forceinline__ int kperm(int wl) {
    int blk = wl >> 3, wi = wl & 7;
    return blk * 8 + ((wi < 4) ? 2 * wi : 2 * (wi - 4) + 1);
}

// ---------------- packing / elementwise kernels ------------------------------
// A natural [2304][2048] fp32 -> packed fp16 [tile18][chunk64][128][24w]
__global__ void packAh(const float* __restrict__ in, uint32_t* __restrict__ out) {
    int i = blockIdx.x * blockDim.x + threadIdx.x;
    if (i >= ROWS * DF / 4) return;
    int e = i * 4;
    int r = e / DF, c = e % DF;
    float4 v = *(const float4*)&in[e];
    uint32_t h0 = packh2(v.x, v.y), h1 = packh2(v.z, v.w);
    size_t rowb = ((size_t)((r >> 7) * 64 + (c >> 5)) * 128 + (r & 127)) * 24;
    int wl = (c & 31) >> 1;
    out[rowb + kperm(wl)]     = h0;
    out[rowb + kperm(wl + 1)] = h1;
}

// W natural [K=2048][ncols] fp32 -> packed fp16 [ntile][chunk64][16][260]
__global__ void packWh(const float* __restrict__ in, uint32_t* __restrict__ out,
                       int ncols) {
    int i = blockIdx.x * blockDim.x + threadIdx.x;
    int nq = ncols / 4;
    if (i >= (DF / 2) * nq) return;
    int n4 = (i % nq) * 4;
    int kk = (i / nq) * 2;
    float4 a = *(const float4*)&in[(size_t)kk * ncols + n4];
    float4 b = *(const float4*)&in[(size_t)(kk + 1) * ncols + n4];
    uint4 w;
    w.x = packh2(a.x, b.x); w.y = packh2(a.y, b.y);
    w.z = packh2(a.z, b.z); w.w = packh2(a.w, b.w);
    int p = kperm((kk & 31) >> 1);
    size_t o = ((size_t)((n4 >> 8) * 64 + (kk >> 5)) * 16 + p) * 260 + (n4 & 255);
    *(uint4*)&out[o] = w;
}

// natural [2304][2048] -> packed RAW fp32 [b64][chunk64][36][40]
__global__ void packRB(const float* __restrict__ in, float* __restrict__ out) {
    int i = blockIdx.x * blockDim.x + threadIdx.x;
    if (i >= ROWS * DF / 4) return;
    int e = i * 4;
    int r = e / DF, c = e % DF;
    int b = r / N_, j = r - b * N_;
    float4 v = *(const float4*)&in[e];
    size_t o = ((size_t)(b * 64 + (c >> 5)) * 36 + j) * 40 + (c & 31);
    *(float4*)&out[o] = v;
}

// tmp1 = tmp1*tmp2 (natural fp32, residual); packed fp16 product -> pfus
__global__ void fusekh(float* __restrict__ a, const float* __restrict__ b,
                       uint32_t* __restrict__ pk) {
    int i = blockIdx.x * blockDim.x + threadIdx.x;
    if (i >= ROWS * DF / 4) return;
    int e = i * 4;
    int r = e / DF, c = e % DF;
    float4 x = *(float4*)&a[e];
    float4 y = *(const float4*)&b[e];
    x.x *= y.x; x.y *= y.y; x.z *= y.z; x.w *= y.w;
    *(float4*)&a[e] = x;
    uint32_t h0 = packh2(x.x, x.y), h1 = packh2(x.z, x.w);
    size_t rowb = ((size_t)((r >> 7) * 64 + (c >> 5)) * 128 + (r & 127)) * 24;
    int wl = (c & 31) >> 1;
    pk[rowb + kperm(wl)]     = h0;
    pk[rowb + kperm(wl + 1)] = h1;
}

// ba = boxes @ Wba, bb = boxes @ Wbb  (K = 4)
__global__ void boxproj(const float* __restrict__ boxes,
                        const float* __restrict__ Wba, const float* __restrict__ Wbb,
                        float* __restrict__ ba, float* __restrict__ bb) {
    int idx = blockIdx.x * blockDim.x + threadIdx.x;
    if (idx >= ROWS * (DF / 4)) return;
    int r  = idx / (DF / 4);
    int dq = (idx % (DF / 4)) * 4;
    float4 bx = *(const float4*)&boxes[r * 4];
    float c[4] = {bx.x, bx.y, bx.z, bx.w};
    float4 sa = make_float4(0.f, 0.f, 0.f, 0.f);
    float4 sb = make_float4(0.f, 0.f, 0.f, 0.f);
#pragma unroll
    for (int cc = 0; cc < 4; cc++) {
        float4 wa = *(const float4*)&Wba[cc * DF + dq];
        float4 wb = *(const float4*)&Wbb[cc * DF + dq];
        sa.x += c[cc] * wa.x; sa.y += c[cc] * wa.y; sa.z += c[cc] * wa.z; sa.w += c[cc] * wa.w;
        sb.x += c[cc] * wb.x; sb.y += c[cc] * wb.y; sb.z += c[cc] * wb.z; sb.w += c[cc] * wb.w;
    }
    *(float4*)&ba[(size_t)r * DF + dq] = sa;
    *(float4*)&bb[(size_t)r * DF + dq] = sb;
}

// ---------------------------------------------------------------------------
// fp16 mma.sync GEMM (fp32 acc), bulk-copy staged packed operands.
// CTA 128x256, 3 stages, K-chunk 32 (2 x K16), 8 warps of 64x64.
// smem words: bars 0..15, As@16 (3xPA_W), Bs@16+3*PA_W (3xPB_W).
// ---------------------------------------------------------------------------
#define G_SMEM ((16 + 3 * PA_W + 3 * PB_W) * 4)
__global__ __launch_bounds__(256)
void gemm_h(const uint32_t* __restrict__ pa, const uint32_t* __restrict__ pb,
            float* __restrict__ C) {
    extern __shared__ uint32_t smw[];
    uint32_t smb = smem_u32(smw);
    const int tid = threadIdx.x, lane = tid & 31, wid = tid >> 5;
    const int cc = lane & 3, q = lane >> 2;
    const int wm = (wid >> 2) * 64, wn = (wid & 3) * 64;
    const int tileM = blockIdx.y, tileN = blockIdx.x;
    const uint32_t* As = smw + 16;
    const uint32_t* Bs = smw + 16 + 3 * PA_W;

    if (tid == 0) {
#pragma unroll
        for (int s = 0; s < 3; s++) MBAR_INIT(smb + 8 * s, 1);
    }
    __syncthreads();

    auto issue = [&](int kc) {
        int s = kc % 3;
        uint32_t bar = smb + 8 * s;
        MBAR_EXPECT(bar, 28928);
        blkcp(smb + (16 + s * PA_W) * 4,
              pa + ((size_t)tileM * 64 + kc) * PA_W, 12288, bar);
        blkcp(smb + (16 + 3 * PA_W + s * PB_W) * 4,
              pb + ((size_t)tileN * 64 + kc) * PB_W, 16640, bar);
    };
    if (tid == 0) { issue(0); issue(1); issue(2); }

    float acc[4][8][4];
#pragma unroll
    for (int i = 0; i < 4; i++)
#pragma unroll
        for (int j = 0; j < 8; j++)
#pragma unroll
            for (int p = 0; p < 4; p++) acc[i][j][p] = 0.f;

    for (int kc = 0; kc < 64; kc++) {
        int s = kc % 3;
        MBAR_WAIT(smb + 8 * s, (kc / 3) & 1);
        const uint32_t* Ab = As + s * PA_W;
        const uint32_t* Bb = Bs + s * PB_W;
#pragma unroll
        for (int kb = 0; kb < 2; kb++) {          // two K16 blocks
            uint32_t af[4][4], bf[8][2];
#pragma unroll
            for (int mf = 0; mf < 4; mf++) {
                int r = wm + mf * 16 + q;
                uint2 lo = *(const uint2*)&Ab[r * 24 + kb * 8 + 2 * cc];
                uint2 hi = *(const uint2*)&Ab[(r + 8) * 24 + kb * 8 + 2 * cc];
                af[mf][0] = lo.x; af[mf][1] = hi.x;
                af[mf][2] = lo.y; af[mf][3] = hi.y;
            }
#pragma unroll
            for (int nf = 0; nf < 8; nf++) {
                int n = wn + nf * 8 + q;
                bf[nf][0] = Bb[(kb * 8 + 2 * cc) * 260 + n];
                bf[nf][1] = Bb[(kb * 8 + 2 * cc + 1) * 260 + n];
            }
#pragma unroll
            for (int mf = 0; mf < 4; mf++)
#pragma unroll
                for (int nf = 0; nf < 8; nf++)
                    mma16(acc[mf][nf], af[mf], bf[nf]);
        }
        __syncthreads();
        if (tid == 0 && kc + 3 < 64) issue(kc + 3);
    }

    const int m0 = tileM * 128, n0 = tileN * 256;
#pragma unroll
    for (int mf = 0; mf < 4; mf++) {
        int r0 = m0 + wm + mf * 16 + q;
#pragma unroll
        for (int nf = 0; nf < 8; nf++) {
            int c = n0 + wn + nf * 8 + 2 * cc;
            *(float2*)&C[(size_t)r0 * DF + c] = make_float2(acc[mf][nf][0], acc[mf][nf][1]);
            *(float2*)&C[(size_t)(r0 + 8) * DF + c] = make_float2(acc[mf][nf][2], acc[mf][nf][3]);
        }
    }
}

// ---------------------------------------------------------------------------
// Relation-attention scores: fp16 mma, G built fp32 in regs -> half2.
// Grid (slice2, ig9, b64), 384 thr, 12 warps (3M x 4N), warp 48x64.
// smem words: bars 0..15, Ws@16 (3xPB_W), rbS@12496 (3xPR_F f32),
//   bbS@16816, raS@21136 (3x160), baS@21616, red@22096 (576). Total 22672 w.
// ---------------------------------------------------------------------------
#define R_SMEM (22672 * 4)
__global__ __launch_bounds__(384)
void relattn_h(const float* __restrict__ pra, const float* __restrict__ prb,
               const float* __restrict__ pba, const float* __restrict__ pbb,
               const uint32_t* __restrict__ pw0, const float* __restrict__ b0,
               const float* __restrict__ W1, float* __restrict__ scp) {
    extern __shared__ uint32_t smw[];
    float* smf = (float*)smw;
    uint32_t smb = smem_u32(smw);
    const uint32_t* Ws = smw + 16;
    const float* rbS = smf + 12496;
    const float* bbS = smf + 16816;
    const float* raS = smf + 21136;
    const float* baS = smf + 21616;
    float* red = smf + 22096;
    const int tid = threadIdx.x, lane = tid & 31, wid = tid >> 5;
    const int cc = lane & 3, q = lane >> 2;
    const int wm = (wid >> 2) * 48, wn = (wid & 3) * 64;
    const int slice = blockIdx.x, ig = blockIdx.y, b = blockIdx.z;

    if (tid == 0) {
#pragma unroll
        for (int s = 0; s < 3; s++) MBAR_INIT(smb + 8 * s, 1);
    }
    __syncthreads();

    int oRBl[3], oRBh[3], oRAl[3], oRAh[3];
#pragma unroll
    for (int mf = 0; mf < 3; mf++) {
        int rl = wm + mf * 16 + q, rh = rl + 8;
        oRBl[mf] = (rl % 36) * 40; oRAl[mf] = (rl / 36) * 40;
        oRBh[mf] = (rh % 36) * 40; oRAh[mf] = (rh / 36) * 40;
    }

    auto issue = [&](int kc) {
        int s = kc % 3;
        uint32_t bar = smb + 8 * s;
        MBAR_EXPECT(bar, 29440);
        blkcp(smb + (16 + s * PB_W) * 4,
              pw0 + ((size_t)slice * 64 + kc) * PB_W, 16640, bar);
        size_t rbase = ((size_t)b * 64 + kc) * PR_F;
        blkcp(smb + (12496 + s * PR_F) * 4, prb + rbase, 5760, bar);
        blkcp(smb + (16816 + s * PR_F) * 4, pbb + rbase, 5760, bar);
        blkcp(smb + (21136 + s * 160) * 4, pra + rbase + ig * 160, 640, bar);
        blkcp(smb + (21616 + s * 160) * 4, pba + rbase + ig * 160, 640, bar);
    };
    if (tid == 0) { issue(0); issue(1); issue(2); }

    float acc[3][8][4];
#pragma unroll
    for (int i = 0; i < 3; i++)
#pragma unroll
        for (int j = 0; j < 8; j++)
#pragma unroll
            for (int p = 0; p < 4; p++) acc[i][j][p] = 0.f;

    for (int kc = 0; kc < 64; kc++) {
        int s = kc % 3;
        MBAR_WAIT(smb + 8 * s, (kc / 3) & 1);
        const uint32_t* Wb = Ws + s * PB_W;
        const float* rs = rbS + s * PR_F;
        const float* bs = bbS + s * PR_F;
        const float* us = raS + s * 160;
        const float* vs = baS + s * 160;
#pragma unroll
        for (int kb = 0; kb < 2; kb++) {
            const int k0 = kb * 16 + 2 * cc;
            uint32_t bf[8][2];
#pragma unroll
            for (int nf = 0; nf < 8; nf++) {
                int n = wn + nf * 8 + q;
                bf[nf][0] = Wb[(kb * 8 + 2 * cc) * 260 + n];
                bf[nf][1] = Wb[(kb * 8 + 2 * cc + 1) * 260 + n];
            }
#pragma unroll
            for (int mf = 0; mf < 3; mf++) {
                float2 rl0 = *(const float2*)&rs[oRBl[mf] + k0];
                float2 rl8 = *(const float2*)&rs[oRBl[mf] + k0 + 8];
                float2 bl0 = *(const float2*)&bs[oRBl[mf] + k0];
                float2 bl8 = *(const float2*)&bs[oRBl[mf] + k0 + 8];
                float2 ul0 = *(const float2*)&us[oRAl[mf] + k0];
                float2 ul8 = *(const float2*)&us[oRAl[mf] + k0 + 8];
                float2 vl0 = *(const float2*)&vs[oRAl[mf] + k0];
                float2 vl8 = *(const float2*)&vs[oRAl[mf] + k0 + 8];
                float2 rh0 = *(const float2*)&rs[oRBh[mf] + k0];
                float2 rh8 = *(const float2*)&rs[oRBh[mf] + k0 + 8];
                float2 bh0 = *(const float2*)&bs[oRBh[mf] + k0];
                float2 bh8 = *(const float2*)&bs[oRBh[mf] + k0 + 8];
                float2 uh0 = *(const float2*)&us[oRAh[mf] + k0];
                float2 uh8 = *(const float2*)&us[oRAh[mf] + k0 + 8];
                float2 vh0 = *(const float2*)&vs[oRAh[mf] + k0];
                float2 vh8 = *(const float2*)&vs[oRAh[mf] + k0 + 8];
                uint32_t af[4];
                af[0] = packh2(fmaf(vl0.x, bl0.x, ul0.x * rl0.x),
                               fmaf(vl0.y, bl0.y, ul0.y * rl0.y));
                af[1] = packh2(fmaf(vh0.x, bh0.x, uh0.x * rh0.x),
                               fmaf(vh0.y, bh0.y, uh0.y * rh0.y));
                af[2] = packh2(fmaf(vl8.x, bl8.x, ul8.x * rl8.x),
                               fmaf(vl8.y, bl8.y, ul8.y * rl8.y));
                af[3] = packh2(fmaf(vh8.x, bh8.x, uh8.x * rh8.x),
                               fmaf(vh8.y, bh8.y, uh8.y * rh8.y));
#pragma unroll
                for (int nf = 0; nf < 8; nf++)
                    mma16(acc[mf][nf], af, bf[nf]);
            }
        }
        __syncthreads();
        if (tid == 0 && kc + 3 < 64) issue(kc + 3);
    }

    // epilogue: partial scores over this 256-col slice (deterministic order)
    const float* b0g = b0 + slice * 256;
    const float* W1g = W1 + slice * 256;
#pragma unroll
    for (int mf = 0; mf < 3; mf++) {
        float s0 = 0.f, s1 = 0.f;
#pragma unroll
        for (int nf = 0; nf < 8; nf++) {
            int c0 = wn + nf * 8 + 2 * cc;
            float w0 = W1g[c0],     e0 = b0g[c0];
            float w1 = W1g[c0 + 1], e1 = b0g[c0 + 1];
            s0 += w0 * tanhf(acc[mf][nf][0] + e0) + w1 * tanhf(acc[mf][nf][1] + e1);
            s1 += w0 * tanhf(acc[mf][nf][2] + e0) + w1 * tanhf(acc[mf][nf][3] + e1);
        }
        s0 += __shfl_xor_sync(0xffffffffu, s0, 1);
        s0 += __shfl_xor_sync(0xffffffffu, s0, 2);
        s1 += __shfl_xor_sync(0xffffffffu, s1, 1);
        s1 += __shfl_xor_sync(0xffffffffu, s1, 2);
        if (cc == 0) {
            int r = wm + mf * 16 + q;
            red[r * 4 + (wid & 3)]       = s0;
            red[(r + 8) * 4 + (wid & 3)] = s1;
        }
    }
    __syncthreads();
    if (tid < 144) {
        float tot = red[tid * 4] + red[tid * 4 + 1] + red[tid * 4 + 2] + red[tid * 4 + 3];
        scp[(((size_t)slice * B_ + b) * 9 + ig) * 144 + tid] = tot;
    }
}

// softmax over j for each (b,i)
__global__ void attk(const float* __restrict__ scp, float* __restrict__ att) {
    int bi = blockIdx.x * blockDim.x + threadIdx.x;
    if (bi >= ROWS) return;
    int b = bi / N_, i = bi - b * N_;
    int ig = i >> 2, il = i & 3;
    float sc[N_];
#pragma unroll 4
    for (int j = 0; j < N_; j++) {
        sc[j] = scp[(((size_t)b) * 9 + ig) * 144 + il * 36 + j]
              + scp[(((size_t)B_ + b) * 9 + ig) * 144 + il * 36 + j];
    }
    float m = sc[0];
    for (int j = 1; j < N_; j++) m = fmaxf(m, sc[j]);
    float sum = 0.f;
    for (int j = 0; j < N_; j++) { sc[j] = expf(sc[j] - m); sum += sc[j]; }
    float inv = 1.f / sum;
    for (int j = 0; j < N_; j++) att[(size_t)bi * N_ + j] = sc[j] * inv;
}

// out = obj + fused + ra.*(att@rb) + ba.*(att@bb)
__global__ __launch_bounds__(256)
void ehat_fin(const float* __restrict__ att,
              const float* __restrict__ ra, const float* __restrict__ rb,
              const float* __restrict__ ba, const float* __restrict__ bb,
              const float* __restrict__ obj, const float* __restrict__ fus,
              float* __restrict__ out) {
    __shared__ float att_s[N_][N_ + 1];
    const int tid = threadIdx.x;
    const int b = blockIdx.y, d0 = blockIdx.x * 128;
    const int d = tid & 127, half = tid >> 7;
    for (int idx = tid; idx < N_ * N_; idx += 256)
        att_s[idx / N_][idx % N_] = att[(size_t)(b * N_ + idx / N_) * N_ + idx % N_];
    __syncthreads();
    const float* rbB = rb + (size_t)b * N_ * DF + d0 + d;
    const float* bbB = bb + (size_t)b * N_ * DF + d0 + d;
    float accR[18], accB[18];
#pragma unroll
    for (int i = 0; i < 18; i++) { accR[i] = 0.f; accB[i] = 0.f; }
    for (int j = 0; j < N_; j++) {
        float rv = rbB[(size_t)j * DF];
        float bv = bbB[(size_t)j * DF];
#pragma unroll
        for (int i = 0; i < 18; i++) {
            float a = att_s[half * 18 + i][j];
            accR[i] += a * rv;
            accB[i] += a * bv;
        }
    }
#pragma unroll
    for (int i = 0; i < 18; i++) {
        size_t row = (size_t)b * N_ + half * 18 + i;
        size_t off = row * DF + d0 + d;
        out[off] = obj[off] + fus[off] + ra[off] * accR[i] + ba[off] * accB[i];
    }
}

extern "C" void kernel_launch(void* const* d_in, const int* in_sizes, int n_in,
                              void* d_out, int out_size) {
    const float* qe    = (const float*)d_in[0];
    const float* obj   = (const float*)d_in[1];
    const float* boxes = (const float*)d_in[2];
    const float* Wq    = (const float*)d_in[3];
    const float* Wo    = (const float*)d_in[4];
    const float* Wfa   = (const float*)d_in[5];
    const float* Wfb   = (const float*)d_in[6];
    const float* Wba   = (const float*)d_in[7];
    const float* Wbb   = (const float*)d_in[8];
    const float* W0    = (const float*)d_in[9];
    const float* b0    = (const float*)d_in[10];
    const float* W1    = (const float*)d_in[11];
    float* out = (float*)d_out;

    float *tmp1, *tmp2, *ra, *rb, *ba, *bb, *pra, *prb, *pba, *pbb, *scp, *attb;
    uint32_t *pqe, *pobj, *pfus, *pWq, *pWo, *pWfa, *pWfb, *pW0;
    cudaGetSymbolAddress((void**)&tmp1, g_tmp1);
    cudaGetSymbolAddress((void**)&tmp2, g_tmp2);
    cudaGetSymbolAddress((void**)&ra,   g_ra);
    cudaGetSymbolAddress((void**)&rb,   g_rb);
    cudaGetSymbolAddress((void**)&ba,   g_ba);
    cudaGetSymbolAddress((void**)&bb,   g_bb);
    cudaGetSymbolAddress((void**)&pqe,  g_pqe);
    cudaGetSymbolAddress((void**)&pobj, g_pobj);
    cudaGetSymbolAddress((void**)&pfus, g_pfus);
    cudaGetSymbolAddress((void**)&pWq,  g_pWq);
    cudaGetSymbolAddress((void**)&pWo,  g_pWo);
    cudaGetSymbolAddress((void**)&pWfa, g_pWfa);
    cudaGetSymbolAddress((void**)&pWfb, g_pWfb);
    cudaGetSymbolAddress((void**)&pW0,  g_pW0);
    cudaGetSymbolAddress((void**)&pra,  g_pra);
    cudaGetSymbolAddress((void**)&prb,  g_prb);
    cudaGetSymbolAddress((void**)&pba,  g_pba);
    cudaGetSymbolAddress((void**)&pbb,  g_pbb);
    cudaGetSymbolAddress((void**)&scp,  g_scp);
    cudaGetSymbolAddress((void**)&attb, g_attb);

    cudaFuncSetAttribute(gemm_h, cudaFuncAttributeMaxDynamicSharedMemorySize, G_SMEM);
    cudaFuncSetAttribute(relattn_h, cudaFuncAttributeMaxDynamicSharedMemorySize, R_SMEM);

    const int nIO  = ROWS * DF / 4;     // 1179648
    const int nWp  = (DF / 2) * (DF / 4);   // 524288
    const int nW0p = (DF / 2) * (DATT / 4); // 131072

    packWh<<<(nWp + 255) / 256, 256>>>(Wq,  pWq,  DF);
    packWh<<<(nWp + 255) / 256, 256>>>(Wo,  pWo,  DF);
    packWh<<<(nWp + 255) / 256, 256>>>(Wfa, pWfa, DF);
    packWh<<<(nWp + 255) / 256, 256>>>(Wfb, pWfb, DF);
    packWh<<<(nW0p + 255) / 256, 256>>>(W0, pW0, DATT);
    packAh<<<(nIO + 255) / 256, 256>>>(qe,  pqe);
    packAh<<<(nIO + 255) / 256, 256>>>(obj, pobj);

    dim3 gg(DF / 256, ROWS / 128);      // (8, 18)
    gemm_h<<<gg, 256, G_SMEM>>>(pqe,  pWq, tmp1);
    gemm_h<<<gg, 256, G_SMEM>>>(pobj, pWo, tmp2);
    fusekh<<<(nIO + 255) / 256, 256>>>(tmp1, tmp2, pfus);
    gemm_h<<<gg, 256, G_SMEM>>>(pfus, pWfa, ra);
    gemm_h<<<gg, 256, G_SMEM>>>(pfus, pWfb, rb);
    boxproj<<<(nIO + 255) / 256, 256>>>(boxes, Wba, Wbb, ba, bb);

    packRB<<<(nIO + 255) / 256, 256>>>(ra, pra);
    packRB<<<(nIO + 255) / 256, 256>>>(rb, prb);
    packRB<<<(nIO + 255) / 256, 256>>>(ba, pba);
    packRB<<<(nIO + 255) / 256, 256>>>(bb, pbb);

    relattn_h<<<dim3(2, 9, B_), 384, R_SMEM>>>(pra, prb, pba, pbb, pW0, b0, W1, scp);
    attk<<<(ROWS + 127) / 128, 128>>>(scp, attb);
    ehat_fin<<<dim3(16, B_), 256>>>(attb, ra, rb, ba, bb, obj, tmp1, out);
}

// round 10
// speedup vs baseline: 1.1354x; 1.1354x over previous
#include <cuda_runtime.h>
#include <math.h>
#include <stdint.h>

#define B_   64
#define N_   36
#define ROWS 2304      // B_*N_
#define DF   2048
#define DATT 512

// packed tile sizes (floats)
#define PA_CH 5120     // 128 x 40
#define PB_CH 8320     // 32 x 260
#define PR_CH 1440     // 36 x 40

// ---------------- scratch (static device buffers) ---------------------------
__device__ float g_tmp1[ROWS * DF];     // qe@Wq, then unrounded fused
__device__ float g_tmp2[ROWS * DF];     // obj@Wo
__device__ float g_ra[ROWS * DF];       // natural outputs
__device__ float g_rb[ROWS * DF];
__device__ float g_ba[ROWS * DF];
__device__ float g_bb[ROWS * DF];
__device__ float g_pqe[18 * 64 * PA_CH];   // packed rna A operands
__device__ float g_pobj[18 * 64 * PA_CH];
__device__ float g_pfus[18 * 64 * PA_CH];
__device__ float g_pWq[8 * 64 * PB_CH];    // packed rna weights
__device__ float g_pWo[8 * 64 * PB_CH];
__device__ float g_pWfa[8 * 64 * PB_CH];
__device__ float g_pWfb[8 * 64 * PB_CH];
__device__ float g_pW0[2 * 64 * PB_CH];
__device__ float g_pra[B_ * 64 * PR_CH];   // packed raw relattn operands
__device__ float g_prb[B_ * 64 * PR_CH];
__device__ float g_pba[B_ * 64 * PR_CH];
__device__ float g_pbb[B_ * 64 * PR_CH];
__device__ float g_scp[2 * 9 * B_ * 144];
__device__ float g_attb[ROWS * N_];

// ---------------- PTX helpers ------------------------------------------------
__device__ __forceinline__ float tf32r(float x) {
    uint32_t u; asm("cvt.rna.tf32.f32 %0, %1;" : "=r"(u) : "f"(x));
    return __uint_as_float(u);
}
__device__ __forceinline__ uint32_t smem_u32(const void* p) {
    uint32_t a;
    asm("{ .reg .u64 t; cvta.to.shared.u64 t, %1; cvt.u32.u64 %0, t; }" : "=r"(a) : "l"(p));
    return a;
}
__device__ __forceinline__ void mma8(float* d, const uint32_t* a, const uint32_t* b) {
    asm volatile("mma.sync.aligned.m16n8k8.row.col.f32.tf32.tf32.f32 "
                 "{%0,%1,%2,%3}, {%4,%5,%6,%7}, {%8,%9}, {%0,%1,%2,%3};"
                 : "+f"(d[0]), "+f"(d[1]), "+f"(d[2]), "+f"(d[3])
                 : "r"(a[0]), "r"(a[1]), "r"(a[2]), "r"(a[3]),
                   "r"(b[0]), "r"(b[1]));
}
__device__ __forceinline__ void blkcp(uint32_t dst, const void* src,
                                      uint32_t bytes, uint32_t bar) {
    asm volatile("cp.async.bulk.shared::cta.global.mbarrier::complete_tx::bytes "
                 "[%0], [%1], %2, [%3];"
                 :: "r"(dst), "l"(src), "r"(bytes), "r"(bar) : "memory");
}
#define MBAR_INIT(a, n) \
    asm volatile("mbarrier.init.shared.b64 [%0], %1;" :: "r"(a), "r"(n) : "memory")
#define MBAR_EXPECT(a, n) \
    asm volatile("mbarrier.arrive.expect_tx.shared.b64 _, [%0], %1;" :: "r"(a), "r"(n) : "memory")
#define MBAR_WAIT(a, ph) do {                                                   \
    uint32_t _m = (a), _p = (ph), _d;                                           \
    asm volatile("{\n\t.reg .pred p;\n\t"                                       \
        "mbarrier.try_wait.parity.acquire.cta.shared::cta.b64 p, [%1], %2;\n\t" \
        "selp.b32 %0, 1, 0, p;\n\t}" : "=r"(_d) : "r"(_m), "r"(_p) : "memory"); \
    if (!_d) {                                                                  \
        asm volatile("{\n\t.reg .pred P;\n\t"                                   \
            "WL_%=:\n\t"                                                        \
            "mbarrier.try_wait.parity.acquire.cta.shared::cta.b64 P, [%0], %1, 0x989680;\n\t" \
            "@P bra.uni WD_%=;\n\t"                                             \
            "bra.uni WL_%=;\n\t"                                                \
            "WD_%=:\n\t}" :: "r"(_m), "r"(_p) : "memory");                      \
    } } while (0)

// ---------------- packing / elementwise kernels ------------------------------
// A natural [2304][2048] -> packed rna [tile18][chunk64][128][40]
__global__ void packA(const float* __restrict__ in, float* __restrict__ out) {
    int i = blockIdx.x * blockDim.x + threadIdx.x;
    if (i >= ROWS * DF / 4) return;
    int e = i * 4;
    int r = e / DF, c = e % DF;
    float4 v = *(const float4*)&in[e];
    v.x = tf32r(v.x); v.y = tf32r(v.y); v.z = tf32r(v.z); v.w = tf32r(v.w);
    size_t o = ((size_t)((r >> 7) * 64 + (c >> 5)) * 128 + (r & 127)) * 40 + (c & 31);
    *(float4*)&out[o] = v;
}

// W natural [2048][2048] -> packed rna [ntile8][chunk64][32][260]
__global__ void packW(const float* __restrict__ in, float* __restrict__ out) {
    int i = blockIdx.x * blockDim.x + threadIdx.x;
    if (i >= DF * DF / 4) return;
    int e = i * 4;
    int k = e / DF, n = e % DF;
    float4 v = *(const float4*)&in[e];
    v.x = tf32r(v.x); v.y = tf32r(v.y); v.z = tf32r(v.z); v.w = tf32r(v.w);
    size_t o = ((size_t)((n >> 8) * 64 + (k >> 5)) * 32 + (k & 31)) * 260 + (n & 255);
    *(float4*)&out[o] = v;
}

// W0 natural [2048][512] -> packed rna [slice2][chunk64][32][260]
__global__ void packW0(const float* __restrict__ in, float* __restrict__ out) {
    int i = blockIdx.x * blockDim.x + threadIdx.x;
    if (i >= DF * DATT / 4) return;
    int e = i * 4;
    int k = e / DATT, n = e % DATT;
    float4 v = *(const float4*)&in[e];
    v.x = tf32r(v.x); v.y = tf32r(v.y); v.z = tf32r(v.z); v.w = tf32r(v.w);
    size_t o = ((size_t)((n >> 8) * 64 + (k >> 5)) * 32 + (k & 31)) * 260 + (n & 255);
    *(float4*)&out[o] = v;
}

// tmp1 = tmp1*tmp2 (natural, residual); packed rna product -> pfus
__global__ void fusek(float* __restrict__ a, const float* __restrict__ b,
                      float* __restrict__ pk) {
    int i = blockIdx.x * blockDim.x + threadIdx.x;
    if (i >= ROWS * DF / 4) return;
    int e = i * 4;
    int r = e / DF, c = e % DF;
    float4 x = *(float4*)&a[e];
    float4 y = *(const float4*)&b[e];
    x.x *= y.x; x.y *= y.y; x.z *= y.z; x.w *= y.w;
    *(float4*)&a[e] = x;
    float4 v;
    v.x = tf32r(x.x); v.y = tf32r(x.y); v.z = tf32r(x.z); v.w = tf32r(x.w);
    size_t o = ((size_t)((r >> 7) * 64 + (c >> 5)) * 128 + (r & 127)) * 40 + (c & 31);
    *(float4*)&pk[o] = v;
}

// ba/bb natural + packed relattn layout, from boxes (K = 4)
__global__ void boxproj(const float* __restrict__ boxes,
                        const float* __restrict__ Wba, const float* __restrict__ Wbb,
                        float* __restrict__ ba, float* __restrict__ bb,
                        float* __restrict__ pba, float* __restrict__ pbb) {
    int idx = blockIdx.x * blockDim.x + threadIdx.x;
    if (idx >= ROWS * (DF / 4)) return;
    int r  = idx / (DF / 4);
    int dq = (idx % (DF / 4)) * 4;
    float4 bx = *(const float4*)&boxes[r * 4];
    float c[4] = {bx.x, bx.y, bx.z, bx.w};
    float4 sa = make_float4(0.f, 0.f, 0.f, 0.f);
    float4 sb = make_float4(0.f, 0.f, 0.f, 0.f);
#pragma unroll
    for (int cc = 0; cc < 4; cc++) {
        float4 wa = *(const float4*)&Wba[cc * DF + dq];
        float4 wb = *(const float4*)&Wbb[cc * DF + dq];
        sa.x += c[cc] * wa.x; sa.y += c[cc] * wa.y; sa.z += c[cc] * wa.z; sa.w += c[cc] * wa.w;
        sb.x += c[cc] * wb.x; sb.y += c[cc] * wb.y; sb.z += c[cc] * wb.z; sb.w += c[cc] * wb.w;
    }
    *(float4*)&ba[(size_t)r * DF + dq] = sa;
    *(float4*)&bb[(size_t)r * DF + dq] = sb;
    int b = r / N_, j = r - b * N_;
    size_t o = ((size_t)(b * 64 + (dq >> 5)) * 36 + j) * 40 + (dq & 31);
    *(float4*)&pba[o] = sa;
    *(float4*)&pbb[o] = sb;
}

// ---------------------------------------------------------------------------
// tf32 mma.sync GEMM, bulk-copy staged from packed operands.
// CTA 128x256, 3-stage pipeline, K-chunk 32, 8 warps of 64x64.
// Optional second output Cp in packed relattn layout [b64][chunk64][36][40].
// ---------------------------------------------------------------------------
#define G_SMEM (40336 * 4)
__global__ __launch_bounds__(256)
void gemm_tc3(const float* __restrict__ pa, const float* __restrict__ pb,
              float* __restrict__ C, float* __restrict__ Cp) {
    extern __shared__ float smf[];
    uint32_t smb = smem_u32(smf);
    const int tid = threadIdx.x, lane = tid & 31, wid = tid >> 5;
    const int cc = lane & 3, q = lane >> 2;
    const int wm = (wid >> 2) * 64, wn = (wid & 3) * 64;
    const int tileM = blockIdx.y, tileN = blockIdx.x;
    float* As = smf + 16;
    float* Bs = smf + 16 + 3 * PA_CH;

    if (tid == 0) {
#pragma unroll
        for (int s = 0; s < 3; s++) MBAR_INIT(smb + 8 * s, 1);
    }
    __syncthreads();

    auto issue = [&](int kc) {
        int s = kc % 3;
        uint32_t bar = smb + 8 * s;
        MBAR_EXPECT(bar, 53760);
        blkcp(smb + (16 + s * PA_CH) * 4,
              pa + ((size_t)tileM * 64 + kc) * PA_CH, 20480, bar);
        blkcp(smb + (16 + 3 * PA_CH + s * PB_CH) * 4,
              pb + ((size_t)tileN * 64 + kc) * PB_CH, 33280, bar);
    };
    if (tid == 0) { issue(0); issue(1); issue(2); }

    float acc[4][8][4];
#pragma unroll
    for (int i = 0; i < 4; i++)
#pragma unroll
        for (int j = 0; j < 8; j++)
#pragma unroll
            for (int p = 0; p < 4; p++) acc[i][j][p] = 0.f;

    for (int kc = 0; kc < 64; kc++) {
        int s = kc % 3;
        MBAR_WAIT(smb + 8 * s, (kc / 3) & 1);
        const float* Ab = As + s * PA_CH;
        const float* Bb = Bs + s * PB_CH;
#pragma unroll
        for (int kb = 0; kb < 32; kb += 8) {
            uint32_t af[4][4], bf[8][2];
#pragma unroll
            for (int mf = 0; mf < 4; mf++) {
                int r = wm + mf * 16 + q;
                float2 lo = *(const float2*)&Ab[r * 40 + kb + 2 * cc];
                float2 hi = *(const float2*)&Ab[(r + 8) * 40 + kb + 2 * cc];
                af[mf][0] = __float_as_uint(lo.x);
                af[mf][1] = __float_as_uint(hi.x);
                af[mf][2] = __float_as_uint(lo.y);
                af[mf][3] = __float_as_uint(hi.y);
            }
#pragma unroll
            for (int nf = 0; nf < 8; nf++) {
                int ci = (kb + 2 * cc) * 260 + wn + nf * 8 + q;
                bf[nf][0] = __float_as_uint(Bb[ci]);
                bf[nf][1] = __float_as_uint(Bb[ci + 260]);
            }
#pragma unroll
            for (int mf = 0; mf < 4; mf++)
#pragma unroll
                for (int nf = 0; nf < 8; nf++)
                    mma8(acc[mf][nf], af[mf], bf[nf]);
        }
        __syncthreads();
        if (tid == 0 && kc + 3 < 64) issue(kc + 3);
    }

    const int m0 = tileM * 128, n0 = tileN * 256;
#pragma unroll
    for (int mf = 0; mf < 4; mf++) {
        int r0 = m0 + wm + mf * 16 + q;
#pragma unroll
        for (int nf = 0; nf < 8; nf++) {
            int c = n0 + wn + nf * 8 + 2 * cc;
            float2 v0 = make_float2(acc[mf][nf][0], acc[mf][nf][1]);
            float2 v1 = make_float2(acc[mf][nf][2], acc[mf][nf][3]);
            *(float2*)&C[(size_t)r0 * DF + c] = v0;
            *(float2*)&C[(size_t)(r0 + 8) * DF + c] = v1;
            if (Cp) {
                int b0i = r0 / 36, j0 = r0 - b0i * 36;
                int b1i = (r0 + 8) / 36, j1 = (r0 + 8) - b1i * 36;
                size_t o0 = ((size_t)(b0i * 64 + (c >> 5)) * 36 + j0) * 40 + (c & 31);
                size_t o1 = ((size_t)(b1i * 64 + (c >> 5)) * 36 + j1) * 40 + (c & 31);
                *(float2*)&Cp[o0] = v0;
                *(float2*)&Cp[o1] = v1;
            }
        }
    }
}

// ---------------------------------------------------------------------------
// Relation-attention scores: 2-STAGE bulk-staged operands (94.5 KB smem ->
// 2 CTAs/SM), G computed in registers (rna).
// Grid (slice2, ig9, b64), 384 threads, 12 warps (3M x 4N), warp 48x64.
// smem words: bars 0..15, Ws@16 (2x8320), rbS@16656 (2x1440), bbS@19536,
//             raS@22416 (2x160), baS@22736, red@23056 (576). Total 23632 w.
// ---------------------------------------------------------------------------
#define R_SMEM (23632 * 4)
__global__ __launch_bounds__(384)
void relattn_blk(const float* __restrict__ pra, const float* __restrict__ prb,
                 const float* __restrict__ pba, const float* __restrict__ pbb,
                 const float* __restrict__ pw0, const float* __restrict__ b0,
                 const float* __restrict__ W1, float* __restrict__ scp) {
    extern __shared__ float smf[];
    uint32_t smb = smem_u32(smf);
    float* Ws  = smf + 16;
    float* rbS = smf + 16656;
    float* bbS = smf + 19536;
    float* raS = smf + 22416;
    float* baS = smf + 22736;
    float* red = smf + 23056;
    const int tid = threadIdx.x, lane = tid & 31, wid = tid >> 5;
    const int cc = lane & 3, q = lane >> 2;
    const int wm = (wid >> 2) * 48, wn = (wid & 3) * 64;
    const int slice = blockIdx.x, ig = blockIdx.y, b = blockIdx.z;

    if (tid == 0) {
        MBAR_INIT(smb + 0, 1);
        MBAR_INIT(smb + 8, 1);
    }
    __syncthreads();

    int oRBl[3], oRBh[3], oRAl[3], oRAh[3];
#pragma unroll
    for (int mf = 0; mf < 3; mf++) {
        int rl = wm + mf * 16 + q, rh = rl + 8;
        oRBl[mf] = (rl % 36) * 40; oRAl[mf] = (rl / 36) * 40;
        oRBh[mf] = (rh % 36) * 40; oRAh[mf] = (rh / 36) * 40;
    }

    auto issue = [&](int kc) {
        int s = kc & 1;
        uint32_t bar = smb + 8 * s;
        MBAR_EXPECT(bar, 46080);
        blkcp(smb + (16 + s * PB_CH) * 4,
              pw0 + ((size_t)slice * 64 + kc) * PB_CH, 33280, bar);
        size_t rbase = ((size_t)b * 64 + kc) * PR_CH;
        blkcp(smb + (16656 + s * PR_CH) * 4, prb + rbase, 5760, bar);
        blkcp(smb + (19536 + s * PR_CH) * 4, pbb + rbase, 5760, bar);
        blkcp(smb + (22416 + s * 160) * 4, pra + rbase + ig * 160, 640, bar);
        blkcp(smb + (22736 + s * 160) * 4, pba + rbase + ig * 160, 640, bar);
    };
    if (tid == 0) { issue(0); issue(1); }

    float acc[3][8][4];
#pragma unroll
    for (int i = 0; i < 3; i++)
#pragma unroll
        for (int j = 0; j < 8; j++)
#pragma unroll
            for (int p = 0; p < 4; p++) acc[i][j][p] = 0.f;

    for (int kc = 0; kc < 64; kc++) {
        int s = kc & 1;
        MBAR_WAIT(smb + 8 * s, (kc / 2) & 1);
        const float* Wb = Ws + s * PB_CH;
        const float* rs = rbS + s * PR_CH;
        const float* bs = bbS + s * PR_CH;
        const float* us = raS + s * 160;
        const float* vs = baS + s * 160;
#pragma unroll
        for (int kb = 0; kb < 32; kb += 8) {
            const int k = kb + 2 * cc;
            uint32_t bf[8][2];
#pragma unroll
            for (int nf = 0; nf < 8; nf++) {
                int ci = k * 260 + wn + nf * 8 + q;
                bf[nf][0] = __float_as_uint(Wb[ci]);
                bf[nf][1] = __float_as_uint(Wb[ci + 260]);
            }
#pragma unroll
            for (int mf = 0; mf < 3; mf++) {
                float2 rv0 = *(const float2*)&rs[oRBl[mf] + k];
                float2 bv0 = *(const float2*)&bs[oRBl[mf] + k];
                float2 u0  = *(const float2*)&us[oRAl[mf] + k];
                float2 v0  = *(const float2*)&vs[oRAl[mf] + k];
                float2 rv1 = *(const float2*)&rs[oRBh[mf] + k];
                float2 bv1 = *(const float2*)&bs[oRBh[mf] + k];
                float2 u1  = *(const float2*)&us[oRAh[mf] + k];
                float2 v1  = *(const float2*)&vs[oRAh[mf] + k];
                uint32_t af[4];
                af[0] = __float_as_uint(tf32r(fmaf(v0.x, bv0.x, u0.x * rv0.x)));
                af[1] = __float_as_uint(tf32r(fmaf(v1.x, bv1.x, u1.x * rv1.x)));
                af[2] = __float_as_uint(tf32r(fmaf(v0.y, bv0.y, u0.y * rv0.y)));
                af[3] = __float_as_uint(tf32r(fmaf(v1.y, bv1.y, u1.y * rv1.y)));
#pragma unroll
                for (int nf = 0; nf < 8; nf++)
                    mma8(acc[mf][nf], af, bf[nf]);
            }
        }
        __syncthreads();
        if (tid == 0 && kc + 2 < 64) issue(kc + 2);
    }

    // epilogue: partial scores over this 256-col slice (deterministic order)
    const float* b0g = b0 + slice * 256;
    const float* W1g = W1 + slice * 256;
#pragma unroll
    for (int mf = 0; mf < 3; mf++) {
        float s0 = 0.f, s1 = 0.f;
#pragma unroll
        for (int nf = 0; nf < 8; nf++) {
            int c0 = wn + nf * 8 + 2 * cc;
            float w0 = W1g[c0],     e0 = b0g[c0];
            float w1 = W1g[c0 + 1], e1 = b0g[c0 + 1];
            s0 += w0 * tanhf(acc[mf][nf][0] + e0) + w1 * tanhf(acc[mf][nf][1] + e1);
            s1 += w0 * tanhf(acc[mf][nf][2] + e0) + w1 * tanhf(acc[mf][nf][3] + e1);
        }
        s0 += __shfl_xor_sync(0xffffffffu, s0, 1);
        s0 += __shfl_xor_sync(0xffffffffu, s0, 2);
        s1 += __shfl_xor_sync(0xffffffffu, s1, 1);
        s1 += __shfl_xor_sync(0xffffffffu, s1, 2);
        if (cc == 0) {
            int r = wm + mf * 16 + q;
            red[r * 4 + (wid & 3)]       = s0;
            red[(r + 8) * 4 + (wid & 3)] = s1;
        }
    }
    __syncthreads();
    if (tid < 144) {
        float tot = red[tid * 4] + red[tid * 4 + 1] + red[tid * 4 + 2] + red[tid * 4 + 3];
        scp[(((size_t)slice * B_ + b) * 9 + ig) * 144 + tid] = tot;
    }
}

// softmax over j for each (b,i)
__global__ void attk(const float* __restrict__ scp, float* __restrict__ att) {
    int bi = blockIdx.x * blockDim.x + threadIdx.x;
    if (bi >= ROWS) return;
    int b = bi / N_, i = bi - b * N_;
    int ig = i >> 2, il = i & 3;
    float sc[N_];
#pragma unroll 4
    for (int j = 0; j < N_; j++) {
        sc[j] = scp[(((size_t)b) * 9 + ig) * 144 + il * 36 + j]
              + scp[(((size_t)B_ + b) * 9 + ig) * 144 + il * 36 + j];
    }
    float m = sc[0];
    for (int j = 1; j < N_; j++) m = fmaxf(m, sc[j]);
    float sum = 0.f;
    for (int j = 0; j < N_; j++) { sc[j] = expf(sc[j] - m); sum += sc[j]; }
    float inv = 1.f / sum;
    for (int j = 0; j < N_; j++) att[(size_t)bi * N_ + j] = sc[j] * inv;
}

// out = obj + fused + ra.*(att@rb) + ba.*(att@bb)
__global__ __launch_bounds__(256)
void ehat_fin(const float* __restrict__ att,
              const float* __restrict__ ra, const float* __restrict__ rb,
              const float* __restrict__ ba, const float* __restrict__ bb,
              const float* __restrict__ obj, const float* __restrict__ fus,
              float* __restrict__ out) {
    __shared__ float att_s[N_][N_ + 1];
    const int tid = threadIdx.x;
    const int b = blockIdx.y, d0 = blockIdx.x * 128;
    const int d = tid & 127, half = tid >> 7;
    for (int idx = tid; idx < N_ * N_; idx += 256)
        att_s[idx / N_][idx % N_] = att[(size_t)(b * N_ + idx / N_) * N_ + idx % N_];
    __syncthreads();
    const float* rbB = rb + (size_t)b * N_ * DF + d0 + d;
    const float* bbB = bb + (size_t)b * N_ * DF + d0 + d;
    float accR[18], accB[18];
#pragma unroll
    for (int i = 0; i < 18; i++) { accR[i] = 0.f; accB[i] = 0.f; }
    for (int j = 0; j < N_; j++) {
        float rv = rbB[(size_t)j * DF];
        float bv = bbB[(size_t)j * DF];
#pragma unroll
        for (int i = 0; i < 18; i++) {
            float a = att_s[half * 18 + i][j];
            accR[i] += a * rv;
            accB[i] += a * bv;
        }
    }
#pragma unroll
    for (int i = 0; i < 18; i++) {
        size_t row = (size_t)b * N_ + half * 18 + i;
        size_t off = row * DF + d0 + d;
        out[off] = obj[off] + fus[off] + ra[off] * accR[i] + ba[off] * accB[i];
    }
}

extern "C" void kernel_launch(void* const* d_in, const int* in_sizes, int n_in,
                              void* d_out, int out_size) {
    const float* qe    = (const float*)d_in[0];
    const float* obj   = (const float*)d_in[1];
    const float* boxes = (const float*)d_in[2];
    const float* Wq    = (const float*)d_in[3];
    const float* Wo    = (const float*)d_in[4];
    const float* Wfa   = (const float*)d_in[5];
    const float* Wfb   = (const float*)d_in[6];
    const float* Wba   = (const float*)d_in[7];
    const float* Wbb   = (const float*)d_in[8];
    const float* W0    = (const float*)d_in[9];
    const float* b0    = (const float*)d_in[10];
    const float* W1    = (const float*)d_in[11];
    float* out = (float*)d_out;

    float *tmp1, *tmp2, *ra, *rb, *ba, *bb;
    float *pqe, *pobj, *pfus, *pWq, *pWo, *pWfa, *pWfb, *pW0;
    float *pra, *prb, *pba, *pbb, *scp, *attb;
    cudaGetSymbolAddress((void**)&tmp1, g_tmp1);
    cudaGetSymbolAddress((void**)&tmp2, g_tmp2);
    cudaGetSymbolAddress((void**)&ra,   g_ra);
    cudaGetSymbolAddress((void**)&rb,   g_rb);
    cudaGetSymbolAddress((void**)&ba,   g_ba);
    cudaGetSymbolAddress((void**)&bb,   g_bb);
    cudaGetSymbolAddress((void**)&pqe,  g_pqe);
    cudaGetSymbolAddress((void**)&pobj, g_pobj);
    cudaGetSymbolAddress((void**)&pfus, g_pfus);
    cudaGetSymbolAddress((void**)&pWq,  g_pWq);
    cudaGetSymbolAddress((void**)&pWo,  g_pWo);
    cudaGetSymbolAddress((void**)&pWfa, g_pWfa);
    cudaGetSymbolAddress((void**)&pWfb, g_pWfb);
    cudaGetSymbolAddress((void**)&pW0,  g_pW0);
    cudaGetSymbolAddress((void**)&pra,  g_pra);
    cudaGetSymbolAddress((void**)&prb,  g_prb);
    cudaGetSymbolAddress((void**)&pba,  g_pba);
    cudaGetSymbolAddress((void**)&pbb,  g_pbb);
    cudaGetSymbolAddress((void**)&scp,  g_scp);
    cudaGetSymbolAddress((void**)&attb, g_attb);

    cudaFuncSetAttribute(gemm_tc3, cudaFuncAttributeMaxDynamicSharedMemorySize, G_SMEM);
    cudaFuncSetAttribute(relattn_blk, cudaFuncAttributeMaxDynamicSharedMemorySize, R_SMEM);

    const int nIO = ROWS * DF / 4;      // 1179648
    const int nW  = DF * DF / 4;        // 1048576
    const int nW0 = DF * DATT / 4;      // 262144

    dim3 gg(DF / 256, ROWS / 128);      // (8, 18)

    // launches 1-5, then #6 = first gemm (lands in the ncu -s 5 -c 1 window)
    packW<<<(nW + 255) / 256, 256>>>(Wq,  pWq);
    packA<<<(nIO + 255) / 256, 256>>>(qe,  pqe);
    packW<<<(nW + 255) / 256, 256>>>(Wo,  pWo);
    packA<<<(nIO + 255) / 256, 256>>>(obj, pobj);
    packW<<<(nW + 255) / 256, 256>>>(Wfa, pWfa);
    gemm_tc3<<<gg, 256, G_SMEM>>>(pqe,  pWq, tmp1, nullptr);   // 6th launch
    packW<<<(nW + 255) / 256, 256>>>(Wfb, pWfb);
    packW0<<<(nW0 + 255) / 256, 256>>>(W0, pW0);
    gemm_tc3<<<gg, 256, G_SMEM>>>(pobj, pWo, tmp2, nullptr);
    fusek<<<(nIO + 255) / 256, 256>>>(tmp1, tmp2, pfus);
    gemm_tc3<<<gg, 256, G_SMEM>>>(pfus, pWfa, ra, pra);
    gemm_tc3<<<gg, 256, G_SMEM>>>(pfus, pWfb, rb, prb);
    boxproj<<<(nIO + 255) / 256, 256>>>(boxes, Wba, Wbb, ba, bb, pba, pbb);

    relattn_blk<<<dim3(2, 9, B_), 384, R_SMEM>>>(pra, prb, pba, pbb, pW0, b0, W1, scp);
    attk<<<(ROWS + 127) / 128, 128>>>(scp, attb);
    ehat_fin<<<dim3(16, B_), 256>>>(attb, ra, rb, ba, bb, obj, tmp1, out);
}

// round 11
// speedup vs baseline: 1.2589x; 1.1088x over previous
#include <cuda_runtime.h>
#include <cuda_fp16.h>
#include <math.h>
#include <stdint.h>

#define B_   64
#define N_   36
#define ROWS 2304      // B_*N_
#define DF   2048
#define DATT 512

// packed chunk sizes
#define PA_W 3072      // fp16 A: 128 rows x 24 words
#define PB_W 4160      // fp16 W: 16 word-rows x 260
#define PB_CH 8320     // fp32 W0: 32 rows x 260 floats
#define PR_CH 1440     // fp32 relattn operands: 36 x 40 floats

// ---------------- scratch ----------------------------------------------------
__device__ float    g_tmp1[ROWS * DF];     // qe@Wq, then unrounded fused
__device__ float    g_tmp2[ROWS * DF];     // obj@Wo
__device__ float    g_ra[ROWS * DF];       // natural outputs
__device__ float    g_rb[ROWS * DF];
__device__ float    g_ba[ROWS * DF];
__device__ float    g_bb[ROWS * DF];
__device__ uint32_t g_pqe[18 * 64 * PA_W];    // packed fp16 A operands
__device__ uint32_t g_pobj[18 * 64 * PA_W];
__device__ uint32_t g_pfus[18 * 64 * PA_W];
__device__ uint32_t g_pWq[8 * 64 * PB_W];     // packed fp16 weights
__device__ uint32_t g_pWo[8 * 64 * PB_W];
__device__ uint32_t g_pWfa[8 * 64 * PB_W];
__device__ uint32_t g_pWfb[8 * 64 * PB_W];
__device__ float    g_pW0[2 * 64 * PB_CH];    // packed rna fp32 W0 (relattn)
__device__ float    g_pra[B_ * 64 * PR_CH];   // packed raw fp32 relattn operands
__device__ float    g_prb[B_ * 64 * PR_CH];
__device__ float    g_pba[B_ * 64 * PR_CH];
__device__ float    g_pbb[B_ * 64 * PR_CH];
__device__ float    g_scp[2 * 9 * B_ * 144];
__device__ float    g_attb[ROWS * N_];

// ---------------- PTX helpers ------------------------------------------------
__device__ __forceinline__ float tf32r(float x) {
    uint32_t u; asm("cvt.rna.tf32.f32 %0, %1;" : "=r"(u) : "f"(x));
    return __uint_as_float(u);
}
__device__ __forceinline__ uint32_t smem_u32(const void* p) {
    uint32_t a;
    asm("{ .reg .u64 t; cvta.to.shared.u64 t, %1; cvt.u32.u64 %0, t; }" : "=r"(a) : "l"(p));
    return a;
}
__device__ __forceinline__ uint32_t packh2(float x, float y) {
    __half2 h = __floats2half2_rn(x, y);
    return *(uint32_t*)&h;
}
__device__ __forceinline__ void mma8(float* d, const uint32_t* a, const uint32_t* b) {
    asm volatile("mma.sync.aligned.m16n8k8.row.col.f32.tf32.tf32.f32 "
                 "{%0,%1,%2,%3}, {%4,%5,%6,%7}, {%8,%9}, {%0,%1,%2,%3};"
                 : "+f"(d[0]), "+f"(d[1]), "+f"(d[2]), "+f"(d[3])
                 : "r"(a[0]), "r"(a[1]), "r"(a[2]), "r"(a[3]),
                   "r"(b[0]), "r"(b[1]));
}
__device__ __forceinline__ void mma16(float* d, const uint32_t* a, const uint32_t* b) {
    asm volatile("mma.sync.aligned.m16n8k16.row.col.f32.f16.f16.f32 "
                 "{%0,%1,%2,%3}, {%4,%5,%6,%7}, {%8,%9}, {%0,%1,%2,%3};"
                 : "+f"(d[0]), "+f"(d[1]), "+f"(d[2]), "+f"(d[3])
                 : "r"(a[0]), "r"(a[1]), "r"(a[2]), "r"(a[3]),
                   "r"(b[0]), "r"(b[1]));
}
__device__ __forceinline__ void blkcp(uint32_t dst, const void* src,
                                      uint32_t bytes, uint32_t bar) {
    asm volatile("cp.async.bulk.shared::cta.global.mbarrier::complete_tx::bytes "
                 "[%0], [%1], %2, [%3];"
                 :: "r"(dst), "l"(src), "r"(bytes), "r"(bar) : "memory");
}
#define MBAR_INIT(a, n) \
    asm volatile("mbarrier.init.shared.b64 [%0], %1;" :: "r"(a), "r"(n) : "memory")
#define MBAR_EXPECT(a, n) \
    asm volatile("mbarrier.arrive.expect_tx.shared.b64 _, [%0], %1;" :: "r"(a), "r"(n) : "memory")
#define MBAR_WAIT(a, ph) do {                                                   \
    uint32_t _m = (a), _p = (ph), _d;                                           \
    asm volatile("{\n\t.reg .pred p;\n\t"                                       \
        "mbarrier.try_wait.parity.acquire.cta.shared::cta.b64 p, [%1], %2;\n\t" \
        "selp.b32 %0, 1, 0, p;\n\t}" : "=r"(_d) : "r"(_m), "r"(_p) : "memory"); \
    if (!_d) {                                                                  \
        asm volatile("{\n\t.reg .pred P;\n\t"                                   \
            "WL_%=:\n\t"                                                        \
            "mbarrier.try_wait.parity.acquire.cta.shared::cta.b64 P, [%0], %1, 0x989680;\n\t" \
            "@P bra.uni WD_%=;\n\t"                                             \
            "bra.uni WL_%=;\n\t"                                                \
            "WD_%=:\n\t}" :: "r"(_m), "r"(_p) : "memory");                      \
    } } while (0)

// k-word permutation within a K=16 block (8 half2 words):
// logical w -> phys (w<4 ? 2w : 2(w-4)+1): fragment pairs adjacent -> LDS.64
__device__ __forceinline__ int kperm(int wl) {
    int blk = wl >> 3, wi = wl & 7;
    return blk * 8 + ((wi < 4) ? 2 * wi : 2 * (wi - 4) + 1);
}

// ---------------- packing / elementwise kernels ------------------------------
// A natural [2304][2048] fp32 -> packed fp16 [tile18][chunk64][128][24w]
__global__ void packAh(const float* __restrict__ in, uint32_t* __restrict__ out) {
    int i = blockIdx.x * blockDim.x + threadIdx.x;
    if (i >= ROWS * DF / 4) return;
    int e = i * 4;
    int r = e / DF, c = e % DF;
    float4 v = *(const float4*)&in[e];
    uint32_t h0 = packh2(v.x, v.y), h1 = packh2(v.z, v.w);
    size_t rowb = ((size_t)((r >> 7) * 64 + (c >> 5)) * 128 + (r & 127)) * 24;
    int wl = (c & 31) >> 1;
    out[rowb + kperm(wl)]     = h0;
    out[rowb + kperm(wl + 1)] = h1;
}

// W natural [K=2048][2048] fp32 -> packed fp16 [ntile8][chunk64][16][260]
__global__ void packWh(const float* __restrict__ in, uint32_t* __restrict__ out) {
    int i = blockIdx.x * blockDim.x + threadIdx.x;
    if (i >= (DF / 2) * (DF / 4)) return;
    int n4 = (i % (DF / 4)) * 4;
    int kk = (i / (DF / 4)) * 2;
    float4 a = *(const float4*)&in[(size_t)kk * DF + n4];
    float4 b = *(const float4*)&in[(size_t)(kk + 1) * DF + n4];
    uint4 w;
    w.x = packh2(a.x, b.x); w.y = packh2(a.y, b.y);
    w.z = packh2(a.z, b.z); w.w = packh2(a.w, b.w);
    int p = kperm((kk & 31) >> 1);
    size_t o = ((size_t)((n4 >> 8) * 64 + (kk >> 5)) * 16 + p) * 260 + (n4 & 255);
    *(uint4*)&out[o] = w;
}

// W0 natural [2048][512] -> packed rna fp32 [slice2][chunk64][32][260]
__global__ void packW0(const float* __restrict__ in, float* __restrict__ out) {
    int i = blockIdx.x * blockDim.x + threadIdx.x;
    if (i >= DF * DATT / 4) return;
    int e = i * 4;
    int k = e / DATT, n = e % DATT;
    float4 v = *(const float4*)&in[e];
    v.x = tf32r(v.x); v.y = tf32r(v.y); v.z = tf32r(v.z); v.w = tf32r(v.w);
    size_t o = ((size_t)((n >> 8) * 64 + (k >> 5)) * 32 + (k & 31)) * 260 + (n & 255);
    *(float4*)&out[o] = v;
}

// tmp1 = tmp1*tmp2 (natural fp32, residual); packed fp16 product -> pfus
__global__ void fusekh(float* __restrict__ a, const float* __restrict__ b,
                       uint32_t* __restrict__ pk) {
    int i = blockIdx.x * blockDim.x + threadIdx.x;
    if (i >= ROWS * DF / 4) return;
    int e = i * 4;
    int r = e / DF, c = e % DF;
    float4 x = *(float4*)&a[e];
    float4 y = *(const float4*)&b[e];
    x.x *= y.x; x.y *= y.y; x.z *= y.z; x.w *= y.w;
    *(float4*)&a[e] = x;
    uint32_t h0 = packh2(x.x, x.y), h1 = packh2(x.z, x.w);
    size_t rowb = ((size_t)((r >> 7) * 64 + (c >> 5)) * 128 + (r & 127)) * 24;
    int wl = (c & 31) >> 1;
    pk[rowb + kperm(wl)]     = h0;
    pk[rowb + kperm(wl + 1)] = h1;
}

// ba/bb natural + packed relattn layout, from boxes (K = 4)
__global__ void boxproj(const float* __restrict__ boxes,
                        const float* __restrict__ Wba, const float* __restrict__ Wbb,
                        float* __restrict__ ba, float* __restrict__ bb,
                        float* __restrict__ pba, float* __restrict__ pbb) {
    int idx = blockIdx.x * blockDim.x + threadIdx.x;
    if (idx >= ROWS * (DF / 4)) return;
    int r  = idx / (DF / 4);
    int dq = (idx % (DF / 4)) * 4;
    float4 bx = *(const float4*)&boxes[r * 4];
    float c[4] = {bx.x, bx.y, bx.z, bx.w};
    float4 sa = make_float4(0.f, 0.f, 0.f, 0.f);
    float4 sb = make_float4(0.f, 0.f, 0.f, 0.f);
#pragma unroll
    for (int cc = 0; cc < 4; cc++) {
        float4 wa = *(const float4*)&Wba[cc * DF + dq];
        float4 wb = *(const float4*)&Wbb[cc * DF + dq];
        sa.x += c[cc] * wa.x; sa.y += c[cc] * wa.y; sa.z += c[cc] * wa.z; sa.w += c[cc] * wa.w;
        sb.x += c[cc] * wb.x; sb.y += c[cc] * wb.y; sb.z += c[cc] * wb.z; sb.w += c[cc] * wb.w;
    }
    *(float4*)&ba[(size_t)r * DF + dq] = sa;
    *(float4*)&bb[(size_t)r * DF + dq] = sb;
    int b = r / N_, j = r - b * N_;
    size_t o = ((size_t)(b * 64 + (dq >> 5)) * 36 + j) * 40 + (dq & 31);
    *(float4*)&pba[o] = sa;
    *(float4*)&pbb[o] = sb;
}

// ---------------------------------------------------------------------------
// fp16 mma.sync GEMM (fp32 acc), bulk-copy staged packed operands.
// CTA 128x256, 3 stages, K-chunk 32 (2 x K16), 8 warps of 64x64.
// Optional second output Cp in packed relattn fp32 layout.
// ---------------------------------------------------------------------------
#define G_SMEM ((16 + 3 * PA_W + 3 * PB_W) * 4)
__global__ __launch_bounds__(256)
void gemm_h(const uint32_t* __restrict__ pa, const uint32_t* __restrict__ pb,
            float* __restrict__ C, float* __restrict__ Cp) {
    extern __shared__ uint32_t smw[];
    uint32_t smb = smem_u32(smw);
    const int tid = threadIdx.x, lane = tid & 31, wid = tid >> 5;
    const int cc = lane & 3, q = lane >> 2;
    const int wm = (wid >> 2) * 64, wn = (wid & 3) * 64;
    const int tileM = blockIdx.y, tileN = blockIdx.x;
    const uint32_t* As = smw + 16;
    const uint32_t* Bs = smw + 16 + 3 * PA_W;

    if (tid == 0) {
#pragma unroll
        for (int s = 0; s < 3; s++) MBAR_INIT(smb + 8 * s, 1);
    }
    __syncthreads();

    auto issue = [&](int kc) {
        int s = kc % 3;
        uint32_t bar = smb + 8 * s;
        MBAR_EXPECT(bar, 28928);
        blkcp(smb + (16 + s * PA_W) * 4,
              pa + ((size_t)tileM * 64 + kc) * PA_W, 12288, bar);
        blkcp(smb + (16 + 3 * PA_W + s * PB_W) * 4,
              pb + ((size_t)tileN * 64 + kc) * PB_W, 16640, bar);
    };
    if (tid == 0) { issue(0); issue(1); issue(2); }

    float acc[4][8][4];
#pragma unroll
    for (int i = 0; i < 4; i++)
#pragma unroll
        for (int j = 0; j < 8; j++)
#pragma unroll
            for (int p = 0; p < 4; p++) acc[i][j][p] = 0.f;

    for (int kc = 0; kc < 64; kc++) {
        int s = kc % 3;
        MBAR_WAIT(smb + 8 * s, (kc / 3) & 1);
        const uint32_t* Ab = As + s * PA_W;
        const uint32_t* Bb = Bs + s * PB_W;
#pragma unroll
        for (int kb = 0; kb < 2; kb++) {
            uint32_t af[4][4], bf[8][2];
#pragma unroll
            for (int mf = 0; mf < 4; mf++) {
                int r = wm + mf * 16 + q;
                uint2 lo = *(const uint2*)&Ab[r * 24 + kb * 8 + 2 * cc];
                uint2 hi = *(const uint2*)&Ab[(r + 8) * 24 + kb * 8 + 2 * cc];
                af[mf][0] = lo.x; af[mf][1] = hi.x;
                af[mf][2] = lo.y; af[mf][3] = hi.y;
            }
#pragma unroll
            for (int nf = 0; nf < 8; nf++) {
                int n = wn + nf * 8 + q;
                bf[nf][0] = Bb[(kb * 8 + 2 * cc) * 260 + n];
                bf[nf][1] = Bb[(kb * 8 + 2 * cc + 1) * 260 + n];
            }
#pragma unroll
            for (int mf = 0; mf < 4; mf++)
#pragma unroll
                for (int nf = 0; nf < 8; nf++)
                    mma16(acc[mf][nf], af[mf], bf[nf]);
        }
        __syncthreads();
        if (tid == 0 && kc + 3 < 64) issue(kc + 3);
    }

    const int m0 = tileM * 128, n0 = tileN * 256;
#pragma unroll
    for (int mf = 0; mf < 4; mf++) {
        int r0 = m0 + wm + mf * 16 + q;
#pragma unroll
        for (int nf = 0; nf < 8; nf++) {
            int c = n0 + wn + nf * 8 + 2 * cc;
            float2 v0 = make_float2(acc[mf][nf][0], acc[mf][nf][1]);
            float2 v1 = make_float2(acc[mf][nf][2], acc[mf][nf][3]);
            *(float2*)&C[(size_t)r0 * DF + c] = v0;
            *(float2*)&C[(size_t)(r0 + 8) * DF + c] = v1;
            if (Cp) {
                int b0i = r0 / 36, j0 = r0 - b0i * 36;
                int b1i = (r0 + 8) / 36, j1 = (r0 + 8) - b1i * 36;
                size_t o0 = ((size_t)(b0i * 64 + (c >> 5)) * 36 + j0) * 40 + (c & 31);
                size_t o1 = ((size_t)(b1i * 64 + (c >> 5)) * 36 + j1) * 40 + (c & 31);
                *(float2*)&Cp[o0] = v0;
                *(float2*)&Cp[o1] = v1;
            }
        }
    }
}

// ---------------------------------------------------------------------------
// Relation-attention scores (round-10 passing version, tf32 mma, 2-stage,
// register G-build). Grid (slice2, ig9, b64), 384 threads.
// ---------------------------------------------------------------------------
#define R_SMEM (23632 * 4)
__global__ __launch_bounds__(384)
void relattn_blk(const float* __restrict__ pra, const float* __restrict__ prb,
                 const float* __restrict__ pba, const float* __restrict__ pbb,
                 const float* __restrict__ pw0, const float* __restrict__ b0,
                 const float* __restrict__ W1, float* __restrict__ scp) {
    extern __shared__ float smf[];
    uint32_t smb = smem_u32(smf);
    float* Ws  = smf + 16;
    float* rbS = smf + 16656;
    float* bbS = smf + 19536;
    float* raS = smf + 22416;
    float* baS = smf + 22736;
    float* red = smf + 23056;
    const int tid = threadIdx.x, lane = tid & 31, wid = tid >> 5;
    const int cc = lane & 3, q = lane >> 2;
    const int wm = (wid >> 2) * 48, wn = (wid & 3) * 64;
    const int slice = blockIdx.x, ig = blockIdx.y, b = blockIdx.z;

    if (tid == 0) {
        MBAR_INIT(smb + 0, 1);
        MBAR_INIT(smb + 8, 1);
    }
    __syncthreads();

    int oRBl[3], oRBh[3], oRAl[3], oRAh[3];
#pragma unroll
    for (int mf = 0; mf < 3; mf++) {
        int rl = wm + mf * 16 + q, rh = rl + 8;
        oRBl[mf] = (rl % 36) * 40; oRAl[mf] = (rl / 36) * 40;
        oRBh[mf] = (rh % 36) * 40; oRAh[mf] = (rh / 36) * 40;
    }

    auto issue = [&](int kc) {
        int s = kc & 1;
        uint32_t bar = smb + 8 * s;
        MBAR_EXPECT(bar, 46080);
        blkcp(smb + (16 + s * PB_CH) * 4,
              pw0 + ((size_t)slice * 64 + kc) * PB_CH, 33280, bar);
        size_t rbase = ((size_t)b * 64 + kc) * PR_CH;
        blkcp(smb + (16656 + s * PR_CH) * 4, prb + rbase, 5760, bar);
        blkcp(smb + (19536 + s * PR_CH) * 4, pbb + rbase, 5760, bar);
        blkcp(smb + (22416 + s * 160) * 4, pra + rbase + ig * 160, 640, bar);
        blkcp(smb + (22736 + s * 160) * 4, pba + rbase + ig * 160, 640, bar);
    };
    if (tid == 0) { issue(0); issue(1); }

    float acc[3][8][4];
#pragma unroll
    for (int i = 0; i < 3; i++)
#pragma unroll
        for (int j = 0; j < 8; j++)
#pragma unroll
            for (int p = 0; p < 4; p++) acc[i][j][p] = 0.f;

    for (int kc = 0; kc < 64; kc++) {
        int s = kc & 1;
        MBAR_WAIT(smb + 8 * s, (kc / 2) & 1);
        const float* Wb = Ws + s * PB_CH;
        const float* rs = rbS + s * PR_CH;
        const float* bs = bbS + s * PR_CH;
        const float* us = raS + s * 160;
        const float* vs = baS + s * 160;
#pragma unroll
        for (int kb = 0; kb < 32; kb += 8) {
            const int k = kb + 2 * cc;
            uint32_t bf[8][2];
#pragma unroll
            for (int nf = 0; nf < 8; nf++) {
                int ci = k * 260 + wn + nf * 8 + q;
                bf[nf][0] = __float_as_uint(Wb[ci]);
                bf[nf][1] = __float_as_uint(Wb[ci + 260]);
            }
#pragma unroll
            for (int mf = 0; mf < 3; mf++) {
                float2 rv0 = *(const float2*)&rs[oRBl[mf] + k];
                float2 bv0 = *(const float2*)&bs[oRBl[mf] + k];
                float2 u0  = *(const float2*)&us[oRAl[mf] + k];
                float2 v0  = *(const float2*)&vs[oRAl[mf] + k];
                float2 rv1 = *(const float2*)&rs[oRBh[mf] + k];
                float2 bv1 = *(const float2*)&bs[oRBh[mf] + k];
                float2 u1  = *(const float2*)&us[oRAh[mf] + k];
                float2 v1  = *(const float2*)&vs[oRAh[mf] + k];
                uint32_t af[4];
                af[0] = __float_as_uint(tf32r(fmaf(v0.x, bv0.x, u0.x * rv0.x)));
                af[1] = __float_as_uint(tf32r(fmaf(v1.x, bv1.x, u1.x * rv1.x)));
                af[2] = __float_as_uint(tf32r(fmaf(v0.y, bv0.y, u0.y * rv0.y)));
                af[3] = __float_as_uint(tf32r(fmaf(v1.y, bv1.y, u1.y * rv1.y)));
#pragma unroll
                for (int nf = 0; nf < 8; nf++)
                    mma8(acc[mf][nf], af, bf[nf]);
            }
        }
        __syncthreads();
        if (tid == 0 && kc + 2 < 64) issue(kc + 2);
    }

    const float* b0g = b0 + slice * 256;
    const float* W1g = W1 + slice * 256;
#pragma unroll
    for (int mf = 0; mf < 3; mf++) {
        float s0 = 0.f, s1 = 0.f;
#pragma unroll
        for (int nf = 0; nf < 8; nf++) {
            int c0 = wn + nf * 8 + 2 * cc;
            float w0 = W1g[c0],     e0 = b0g[c0];
            float w1 = W1g[c0 + 1], e1 = b0g[c0 + 1];
            s0 += w0 * tanhf(acc[mf][nf][0] + e0) + w1 * tanhf(acc[mf][nf][1] + e1);
            s1 += w0 * tanhf(acc[mf][nf][2] + e0) + w1 * tanhf(acc[mf][nf][3] + e1);
        }
        s0 += __shfl_xor_sync(0xffffffffu, s0, 1);
        s0 += __shfl_xor_sync(0xffffffffu, s0, 2);
        s1 += __shfl_xor_sync(0xffffffffu, s1, 1);
        s1 += __shfl_xor_sync(0xffffffffu, s1, 2);
        if (cc == 0) {
            int r = wm + mf * 16 + q;
            red[r * 4 + (wid & 3)]       = s0;
            red[(r + 8) * 4 + (wid & 3)] = s1;
        }
    }
    __syncthreads();
    if (tid < 144) {
        float tot = red[tid * 4] + red[tid * 4 + 1] + red[tid * 4 + 2] + red[tid * 4 + 3];
        scp[(((size_t)slice * B_ + b) * 9 + ig) * 144 + tid] = tot;
    }
}

// softmax over j for each (b,i)
__global__ void attk(const float* __restrict__ scp, float* __restrict__ att) {
    int bi = blockIdx.x * blockDim.x + threadIdx.x;
    if (bi >= ROWS) return;
    int b = bi / N_, i = bi - b * N_;
    int ig = i >> 2, il = i & 3;
    float sc[N_];
#pragma unroll 4
    for (int j = 0; j < N_; j++) {
        sc[j] = scp[(((size_t)b) * 9 + ig) * 144 + il * 36 + j]
              + scp[(((size_t)B_ + b) * 9 + ig) * 144 + il * 36 + j];
    }
    float m = sc[0];
    for (int j = 1; j < N_; j++) m = fmaxf(m, sc[j]);
    float sum = 0.f;
    for (int j = 0; j < N_; j++) { sc[j] = expf(sc[j] - m); sum += sc[j]; }
    float inv = 1.f / sum;
    for (int j = 0; j < N_; j++) att[(size_t)bi * N_ + j] = sc[j] * inv;
}

// out = obj + fused + ra.*(att@rb) + ba.*(att@bb)
__global__ __launch_bounds__(256)
void ehat_fin(const float* __restrict__ att,
              const float* __restrict__ ra, const float* __restrict__ rb,
              const float* __restrict__ ba, const float* __restrict__ bb,
              const float* __restrict__ obj, const float* __restrict__ fus,
              float* __restrict__ out) {
    __shared__ float att_s[N_][N_ + 1];
    const int tid = threadIdx.x;
    const int b = blockIdx.y, d0 = blockIdx.x * 128;
    const int d = tid & 127, half = tid >> 7;
    for (int idx = tid; idx < N_ * N_; idx += 256)
        att_s[idx / N_][idx % N_] = att[(size_t)(b * N_ + idx / N_) * N_ + idx % N_];
    __syncthreads();
    const float* rbB = rb + (size_t)b * N_ * DF + d0 + d;
    const float* bbB = bb + (size_t)b * N_ * DF + d0 + d;
    float accR[18], accB[18];
#pragma unroll
    for (int i = 0; i < 18; i++) { accR[i] = 0.f; accB[i] = 0.f; }
    for (int j = 0; j < N_; j++) {
        float rv = rbB[(size_t)j * DF];
        float bv = bbB[(size_t)j * DF];
#pragma unroll
        for (int i = 0; i < 18; i++) {
            float a = att_s[half * 18 + i][j];
            accR[i] += a * rv;
            accB[i] += a * bv;
        }
    }
#pragma unroll
    for (int i = 0; i < 18; i++) {
        size_t row = (size_t)b * N_ + half * 18 + i;
        size_t off = row * DF + d0 + d;
        out[off] = obj[off] + fus[off] + ra[off] * accR[i] + ba[off] * accB[i];
    }
}

extern "C" void kernel_launch(void* const* d_in, const int* in_sizes, int n_in,
                              void* d_out, int out_size) {
    const float* qe    = (const float*)d_in[0];
    const float* obj   = (const float*)d_in[1];
    const float* boxes = (const float*)d_in[2];
    const float* Wq    = (const float*)d_in[3];
    const float* Wo    = (const float*)d_in[4];
    const float* Wfa   = (const float*)d_in[5];
    const float* Wfb   = (const float*)d_in[6];
    const float* Wba   = (const float*)d_in[7];
    const float* Wbb   = (const float*)d_in[8];
    const float* W0    = (const float*)d_in[9];
    const float* b0    = (const float*)d_in[10];
    const float* W1    = (const float*)d_in[11];
    float* out = (float*)d_out;

    float *tmp1, *tmp2, *ra, *rb, *ba, *bb;
    float *pW0, *pra, *prb, *pba, *pbb, *scp, *attb;
    uint32_t *pqe, *pobj, *pfus, *pWq, *pWo, *pWfa, *pWfb;
    cudaGetSymbolAddress((void**)&tmp1, g_tmp1);
    cudaGetSymbolAddress((void**)&tmp2, g_tmp2);
    cudaGetSymbolAddress((void**)&ra,   g_ra);
    cudaGetSymbolAddress((void**)&rb,   g_rb);
    cudaGetSymbolAddress((void**)&ba,   g_ba);
    cudaGetSymbolAddress((void**)&bb,   g_bb);
    cudaGetSymbolAddress((void**)&pqe,  g_pqe);
    cudaGetSymbolAddress((void**)&pobj, g_pobj);
    cudaGetSymbolAddress((void**)&pfus, g_pfus);
    cudaGetSymbolAddress((void**)&pWq,  g_pWq);
    cudaGetSymbolAddress((void**)&pWo,  g_pWo);
    cudaGetSymbolAddress((void**)&pWfa, g_pWfa);
    cudaGetSymbolAddress((void**)&pWfb, g_pWfb);
    cudaGetSymbolAddress((void**)&pW0,  g_pW0);
    cudaGetSymbolAddress((void**)&pra,  g_pra);
    cudaGetSymbolAddress((void**)&prb,  g_prb);
    cudaGetSymbolAddress((void**)&pba,  g_pba);
    cudaGetSymbolAddress((void**)&pbb,  g_pbb);
    cudaGetSymbolAddress((void**)&scp,  g_scp);
    cudaGetSymbolAddress((void**)&attb, g_attb);

    cudaFuncSetAttribute(gemm_h, cudaFuncAttributeMaxDynamicSharedMemorySize, G_SMEM);
    cudaFuncSetAttribute(relattn_blk, cudaFuncAttributeMaxDynamicSharedMemorySize, R_SMEM);

    const int nIO  = ROWS * DF / 4;        // 1179648
    const int nWp  = (DF / 2) * (DF / 4);  // 524288
    const int nW0  = DF * DATT / 4;        // 262144

    dim3 gg(DF / 256, ROWS / 128);         // (8, 18)

    packWh<<<(nWp + 255) / 256, 256>>>(Wq,  pWq);
    packAh<<<(nIO + 255) / 256, 256>>>(qe,  pqe);
    packWh<<<(nWp + 255) / 256, 256>>>(Wo,  pWo);
    packAh<<<(nIO + 255) / 256, 256>>>(obj, pobj);
    packWh<<<(nWp + 255) / 256, 256>>>(Wfa, pWfa);
    gemm_h<<<gg, 256, G_SMEM>>>(pqe,  pWq, tmp1, nullptr);   // 6th launch
    packWh<<<(nWp + 255) / 256, 256>>>(Wfb, pWfb);
    packW0<<<(nW0 + 255) / 256, 256>>>(W0, pW0);
    gemm_h<<<gg, 256, G_SMEM>>>(pobj, pWo, tmp2, nullptr);
    fusekh<<<(nIO + 255) / 256, 256>>>(tmp1, tmp2, pfus);
    gemm_h<<<gg, 256, G_SMEM>>>(pfus, pWfa, ra, pra);
    gemm_h<<<gg, 256, G_SMEM>>>(pfus, pWfb, rb, prb);
    boxproj<<<(nIO + 255) / 256, 256>>>(boxes, Wba, Wbb, ba, bb, pba, pbb);

    relattn_blk<<<dim3(2, 9, B_), 384, R_SMEM>>>(pra, prb, pba, pbb, pW0, b0, W1, scp);
    attk<<<(ROWS + 127) / 128, 128>>>(scp, attb);
    ehat_fin<<<dim3(16, B_), 256>>>(attb, ra, rb, ba, bb, obj, tmp1, out);
}

// round 12
// speedup vs baseline: 1.7729x; 1.4083x over previous
#include <cuda_runtime.h>
#include <cuda_fp16.h>
#include <math.h>
#include <stdint.h>

#define B_   64
#define N_   36
#define ROWS 2304      // B_*N_
#define DF   2048
#define DATT 512

// packed chunk sizes
#define PA_W 3072      // fp16 A: 128 rows x 24 words
#define PB_W 4160      // fp16 W: 16 word-rows x 260
#define PR_CH 1440     // fp32 relattn operands: 36 x 40 floats

// ---------------- scratch ----------------------------------------------------
__device__ float    g_tmp1[ROWS * DF];     // qe@Wq, then unrounded fused
__device__ float    g_tmp2[ROWS * DF];     // obj@Wo
__device__ float    g_ra[ROWS * DF];       // natural outputs
__device__ float    g_rb[ROWS * DF];
__device__ float    g_ba[ROWS * DF];
__device__ float    g_bb[ROWS * DF];
__device__ uint32_t g_pqe[18 * 64 * PA_W];    // packed fp16 A operands
__device__ uint32_t g_pobj[18 * 64 * PA_W];
__device__ uint32_t g_pfus[18 * 64 * PA_W];
__device__ uint32_t g_pWq[8 * 64 * PB_W];     // packed fp16 weights
__device__ uint32_t g_pWo[8 * 64 * PB_W];
__device__ uint32_t g_pWfa[8 * 64 * PB_W];
__device__ uint32_t g_pWfb[8 * 64 * PB_W];
__device__ uint32_t g_pW0h[2 * 64 * PB_W];    // packed fp16 W0 (relattn)
__device__ float    g_pra[B_ * 64 * PR_CH];   // packed raw fp32 relattn operands
__device__ float    g_prb[B_ * 64 * PR_CH];
__device__ float    g_pba[B_ * 64 * PR_CH];
__device__ float    g_pbb[B_ * 64 * PR_CH];
__device__ float    g_scp[2 * 9 * B_ * 144];
__device__ float    g_attb[ROWS * N_];

// ---------------- PTX helpers ------------------------------------------------
__device__ __forceinline__ uint32_t smem_u32(const void* p) {
    uint32_t a;
    asm("{ .reg .u64 t; cvta.to.shared.u64 t, %1; cvt.u32.u64 %0, t; }" : "=r"(a) : "l"(p));
    return a;
}
__device__ __forceinline__ uint32_t packh2(float x, float y) {
    __half2 h = __floats2half2_rn(x, y);
    return *(uint32_t*)&h;
}
__device__ __forceinline__ void mma16(float* d, const uint32_t* a, const uint32_t* b) {
    asm volatile("mma.sync.aligned.m16n8k16.row.col.f32.f16.f16.f32 "
                 "{%0,%1,%2,%3}, {%4,%5,%6,%7}, {%8,%9}, {%0,%1,%2,%3};"
                 : "+f"(d[0]), "+f"(d[1]), "+f"(d[2]), "+f"(d[3])
                 : "r"(a[0]), "r"(a[1]), "r"(a[2]), "r"(a[3]),
                   "r"(b[0]), "r"(b[1]));
}
__device__ __forceinline__ void blkcp(uint32_t dst, const void* src,
                                      uint32_t bytes, uint32_t bar) {
    asm volatile("cp.async.bulk.shared::cta.global.mbarrier::complete_tx::bytes "
                 "[%0], [%1], %2, [%3];"
                 :: "r"(dst), "l"(src), "r"(bytes), "r"(bar) : "memory");
}
#define MBAR_INIT(a, n) \
    asm volatile("mbarrier.init.shared.b64 [%0], %1;" :: "r"(a), "r"(n) : "memory")
#define MBAR_EXPECT(a, n) \
    asm volatile("mbarrier.arrive.expect_tx.shared.b64 _, [%0], %1;" :: "r"(a), "r"(n) : "memory")
#define MBAR_WAIT(a, ph) do {                                                   \
    uint32_t _m = (a), _p = (ph), _d;                                           \
    asm volatile("{\n\t.reg .pred p;\n\t"                                       \
        "mbarrier.try_wait.parity.acquire.cta.shared::cta.b64 p, [%1], %2;\n\t" \
        "selp.b32 %0, 1, 0, p;\n\t}" : "=r"(_d) : "r"(_m), "r"(_p) : "memory"); \
    if (!_d) {                                                                  \
        asm volatile("{\n\t.reg .pred P;\n\t"                                   \
            "WL_%=:\n\t"                                                        \
            "mbarrier.try_wait.parity.acquire.cta.shared::cta.b64 P, [%0], %1, 0x989680;\n\t" \
            "@P bra.uni WD_%=;\n\t"                                             \
            "bra.uni WL_%=;\n\t"                                                \
            "WD_%=:\n\t}" :: "r"(_m), "r"(_p) : "memory");                      \
    } } while (0)

// k-word permutation within a K=16 block (8 half2 words):
// logical w -> phys (w<4 ? 2w : 2(w-4)+1): fragment pairs adjacent -> LDS.64
__device__ __forceinline__ int kperm(int wl) {
    int blk = wl >> 3, wi = wl & 7;
    return blk * 8 + ((wi < 4) ? 2 * wi : 2 * (wi - 4) + 1);
}

// ---------------- packing / elementwise kernels ------------------------------
// A natural [2304][2048] fp32 -> packed fp16 [tile18][chunk64][128][24w]
__global__ void packAh(const float* __restrict__ in, uint32_t* __restrict__ out) {
    int i = blockIdx.x * blockDim.x + threadIdx.x;
    if (i >= ROWS * DF / 4) return;
    int e = i * 4;
    int r = e / DF, c = e % DF;
    float4 v = *(const float4*)&in[e];
    uint32_t h0 = packh2(v.x, v.y), h1 = packh2(v.z, v.w);
    size_t rowb = ((size_t)((r >> 7) * 64 + (c >> 5)) * 128 + (r & 127)) * 24;
    int wl = (c & 31) >> 1;
    out[rowb + kperm(wl)]     = h0;
    out[rowb + kperm(wl + 1)] = h1;
}

// W natural [K=2048][ncols] fp32 -> packed fp16 [ntile][chunk64][16][260]
__global__ void packWh(const float* __restrict__ in, uint32_t* __restrict__ out,
                       int ncols) {
    int i = blockIdx.x * blockDim.x + threadIdx.x;
    int nq = ncols / 4;
    if (i >= (DF / 2) * nq) return;
    int n4 = (i % nq) * 4;
    int kk = (i / nq) * 2;
    float4 a = *(const float4*)&in[(size_t)kk * ncols + n4];
    float4 b = *(const float4*)&in[(size_t)(kk + 1) * ncols + n4];
    uint4 w;
    w.x = packh2(a.x, b.x); w.y = packh2(a.y, b.y);
    w.z = packh2(a.z, b.z); w.w = packh2(a.w, b.w);
    int p = kperm((kk & 31) >> 1);
    size_t o = ((size_t)((n4 >> 8) * 64 + (kk >> 5)) * 16 + p) * 260 + (n4 & 255);
    *(uint4*)&out[o] = w;
}

// tmp1 = tmp1*tmp2 (natural fp32, residual); packed fp16 product -> pfus
__global__ void fusekh(float* __restrict__ a, const float* __restrict__ b,
                       uint32_t* __restrict__ pk) {
    int i = blockIdx.x * blockDim.x + threadIdx.x;
    if (i >= ROWS * DF / 4) return;
    int e = i * 4;
    int r = e / DF, c = e % DF;
    float4 x = *(float4*)&a[e];
    float4 y = *(const float4*)&b[e];
    x.x *= y.x; x.y *= y.y; x.z *= y.z; x.w *= y.w;
    *(float4*)&a[e] = x;
    uint32_t h0 = packh2(x.x, x.y), h1 = packh2(x.z, x.w);
    size_t rowb = ((size_t)((r >> 7) * 64 + (c >> 5)) * 128 + (r & 127)) * 24;
    int wl = (c & 31) >> 1;
    pk[rowb + kperm(wl)]     = h0;
    pk[rowb + kperm(wl + 1)] = h1;
}

// ba/bb natural + packed relattn layout, from boxes (K = 4)
__global__ void boxproj(const float* __restrict__ boxes,
                        const float* __restrict__ Wba, const float* __restrict__ Wbb,
                        float* __restrict__ ba, float* __restrict__ bb,
                        float* __restrict__ pba, float* __restrict__ pbb) {
    int idx = blockIdx.x * blockDim.x + threadIdx.x;
    if (idx >= ROWS * (DF / 4)) return;
    int r  = idx / (DF / 4);
    int dq = (idx % (DF / 4)) * 4;
    float4 bx = *(const float4*)&boxes[r * 4];
    float c[4] = {bx.x, bx.y, bx.z, bx.w};
    float4 sa = make_float4(0.f, 0.f, 0.f, 0.f);
    float4 sb = make_float4(0.f, 0.f, 0.f, 0.f);
#pragma unroll
    for (int cc = 0; cc < 4; cc++) {
        float4 wa = *(const float4*)&Wba[cc * DF + dq];
        float4 wb = *(const float4*)&Wbb[cc * DF + dq];
        sa.x += c[cc] * wa.x; sa.y += c[cc] * wa.y; sa.z += c[cc] * wa.z; sa.w += c[cc] * wa.w;
        sb.x += c[cc] * wb.x; sb.y += c[cc] * wb.y; sb.z += c[cc] * wb.z; sb.w += c[cc] * wb.w;
    }
    *(float4*)&ba[(size_t)r * DF + dq] = sa;
    *(float4*)&bb[(size_t)r * DF + dq] = sb;
    int b = r / N_, j = r - b * N_;
    size_t o = ((size_t)(b * 64 + (dq >> 5)) * 36 + j) * 40 + (dq & 31);
    *(float4*)&pba[o] = sa;
    *(float4*)&pbb[o] = sb;
}

// ---------------------------------------------------------------------------
// fp16 mma.sync GEMM (fp32 acc), bulk-copy staged packed operands.
// CTA 128x256, 3 stages, K-chunk 32 (2 x K16), 8 warps of 64x64.
// Optional second output Cp in packed relattn fp32 layout.
// ---------------------------------------------------------------------------
#define G_SMEM ((16 + 3 * PA_W + 3 * PB_W) * 4)
__global__ __launch_bounds__(256)
void gemm_h(const uint32_t* __restrict__ pa, const uint32_t* __restrict__ pb,
            float* __restrict__ C, float* __restrict__ Cp) {
    extern __shared__ uint32_t smw[];
    uint32_t smb = smem_u32(smw);
    const int tid = threadIdx.x, lane = tid & 31, wid = tid >> 5;
    const int cc = lane & 3, q = lane >> 2;
    const int wm = (wid >> 2) * 64, wn = (wid & 3) * 64;
    const int tileM = blockIdx.y, tileN = blockIdx.x;
    const uint32_t* As = smw + 16;
    const uint32_t* Bs = smw + 16 + 3 * PA_W;

    if (tid == 0) {
#pragma unroll
        for (int s = 0; s < 3; s++) MBAR_INIT(smb + 8 * s, 1);
    }
    __syncthreads();

    auto issue = [&](int kc) {
        int s = kc % 3;
        uint32_t bar = smb + 8 * s;
        MBAR_EXPECT(bar, 28928);
        blkcp(smb + (16 + s * PA_W) * 4,
              pa + ((size_t)tileM * 64 + kc) * PA_W, 12288, bar);
        blkcp(smb + (16 + 3 * PA_W + s * PB_W) * 4,
              pb + ((size_t)tileN * 64 + kc) * PB_W, 16640, bar);
    };
    if (tid == 0) { issue(0); issue(1); issue(2); }

    float acc[4][8][4];
#pragma unroll
    for (int i = 0; i < 4; i++)
#pragma unroll
        for (int j = 0; j < 8; j++)
#pragma unroll
            for (int p = 0; p < 4; p++) acc[i][j][p] = 0.f;

    for (int kc = 0; kc < 64; kc++) {
        int s = kc % 3;
        MBAR_WAIT(smb + 8 * s, (kc / 3) & 1);
        const uint32_t* Ab = As + s * PA_W;
        const uint32_t* Bb = Bs + s * PB_W;
#pragma unroll
        for (int kb = 0; kb < 2; kb++) {
            uint32_t af[4][4], bf[8][2];
#pragma unroll
            for (int mf = 0; mf < 4; mf++) {
                int r = wm + mf * 16 + q;
                uint2 lo = *(const uint2*)&Ab[r * 24 + kb * 8 + 2 * cc];
                uint2 hi = *(const uint2*)&Ab[(r + 8) * 24 + kb * 8 + 2 * cc];
                af[mf][0] = lo.x; af[mf][1] = hi.x;
                af[mf][2] = lo.y; af[mf][3] = hi.y;
            }
#pragma unroll
            for (int nf = 0; nf < 8; nf++) {
                int n = wn + nf * 8 + q;
                bf[nf][0] = Bb[(kb * 8 + 2 * cc) * 260 + n];
                bf[nf][1] = Bb[(kb * 8 + 2 * cc + 1) * 260 + n];
            }
#pragma unroll
            for (int mf = 0; mf < 4; mf++)
#pragma unroll
                for (int nf = 0; nf < 8; nf++)
                    mma16(acc[mf][nf], af[mf], bf[nf]);
        }
        __syncthreads();
        if (tid == 0 && kc + 3 < 64) issue(kc + 3);
    }

    const int m0 = tileM * 128, n0 = tileN * 256;
#pragma unroll
    for (int mf = 0; mf < 4; mf++) {
        int r0 = m0 + wm + mf * 16 + q;
#pragma unroll
        for (int nf = 0; nf < 8; nf++) {
            int c = n0 + wn + nf * 8 + 2 * cc;
            float2 v0 = make_float2(acc[mf][nf][0], acc[mf][nf][1]);
            float2 v1 = make_float2(acc[mf][nf][2], acc[mf][nf][3]);
            *(float2*)&C[(size_t)r0 * DF + c] = v0;
            *(float2*)&C[(size_t)(r0 + 8) * DF + c] = v1;
            if (Cp) {
                int b0i = r0 / 36, j0 = r0 - b0i * 36;
                int b1i = (r0 + 8) / 36, j1 = (r0 + 8) - b1i * 36;
                size_t o0 = ((size_t)(b0i * 64 + (c >> 5)) * 36 + j0) * 40 + (c & 31);
                size_t o1 = ((size_t)(b1i * 64 + (c >> 5)) * 36 + j1) * 40 + (c & 31);
                *(float2*)&Cp[o0] = v0;
                *(float2*)&Cp[o1] = v1;
            }
        }
    }
}

// ---------------------------------------------------------------------------
// Relation-attention scores, fp16 mma + smem G-build.
// Grid (slice2, ig9, b64), 384 threads, 12 warps (3M x 4N), warp 48x64.
// Per chunk: stage raw fp32 operands (bulk), build half2 G [144][24w] in smem
// (k-permuted, same fragment pattern as gemm_h), then 2xK16 mma phase.
// smem words: bars 0..15, Ws@16 (2x4160 fp16 W0), rbS@8336 (2x1440 f32),
//   bbS@11216, raS@14096 (2x160), baS@14416, Gs@14736 (2x3456), red@21648.
// Total 22224 words = 88.9 KB.
// ---------------------------------------------------------------------------
#define R_SMEM (22224 * 4)
__global__ __launch_bounds__(384)
void relattn_h2(const float* __restrict__ pra, const float* __restrict__ prb,
                const float* __restrict__ pba, const float* __restrict__ pbb,
                const uint32_t* __restrict__ pw0, const float* __restrict__ b0,
                const float* __restrict__ W1, float* __restrict__ scp) {
    extern __shared__ uint32_t smw[];
    float* smf = (float*)smw;
    uint32_t smb = smem_u32(smw);
    const uint32_t* Ws = smw + 16;
    const float* rbS = smf + 8336;
    const float* bbS = smf + 11216;
    const float* raS = smf + 14096;
    const float* baS = smf + 14416;
    uint32_t* Gs = smw + 14736;
    float* red = smf + 21648;
    const int tid = threadIdx.x, lane = tid & 31, wid = tid >> 5;
    const int cc = lane & 3, q = lane >> 2;
    const int wm = (wid >> 2) * 48, wn = (wid & 3) * 64;
    const int slice = blockIdx.x, ig = blockIdx.y, b = blockIdx.z;

    if (tid == 0) {
        MBAR_INIT(smb + 0, 1);
        MBAR_INIT(smb + 8, 1);
    }
    __syncthreads();

    auto issue = [&](int kc) {
        int s = kc & 1;
        uint32_t bar = smb + 8 * s;
        MBAR_EXPECT(bar, 29440);
        blkcp(smb + (16 + s * PB_W) * 4,
              pw0 + ((size_t)slice * 64 + kc) * PB_W, 16640, bar);
        size_t rbase = ((size_t)b * 64 + kc) * PR_CH;
        blkcp(smb + (8336 + s * PR_CH) * 4, prb + rbase, 5760, bar);
        blkcp(smb + (11216 + s * PR_CH) * 4, pbb + rbase, 5760, bar);
        blkcp(smb + (14096 + s * 160) * 4, pra + rbase + ig * 160, 640, bar);
        blkcp(smb + (14416 + s * 160) * 4, pba + rbase + ig * 160, 640, bar);
    };
    if (tid == 0) { issue(0); issue(1); }

    float acc[3][8][4];
#pragma unroll
    for (int i = 0; i < 3; i++)
#pragma unroll
        for (int j = 0; j < 8; j++)
#pragma unroll
            for (int p = 0; p < 4; p++) acc[i][j][p] = 0.f;

    for (int kc = 0; kc < 64; kc++) {
        int s = kc & 1;
        MBAR_WAIT(smb + 8 * s, (kc / 2) & 1);
        // ---- build half2 G chunk [144 rows][16 logical words, k-permuted] ----
        {
            const float* rs = rbS + s * PR_CH;
            const float* bs = bbS + s * PR_CH;
            const float* us = raS + s * 160;
            const float* vs = baS + s * 160;
            uint32_t* Gw = Gs + s * 3456;
#pragma unroll
            for (int p = 0; p < 6; p++) {
                int idx = tid + 384 * p;       // < 2304
                int r = idx >> 4, wl = idx & 15;
                int il = r / 36, j = r - il * 36;
                int k = 2 * wl;
                float2 rv = *(const float2*)&rs[j * 40 + k];
                float2 bv = *(const float2*)&bs[j * 40 + k];
                float2 u  = *(const float2*)&us[il * 40 + k];
                float2 v  = *(const float2*)&vs[il * 40 + k];
                float g0 = fmaf(v.x, bv.x, u.x * rv.x);
                float g1 = fmaf(v.y, bv.y, u.y * rv.y);
                Gw[r * 24 + kperm(wl)] = packh2(g0, g1);
            }
        }
        __syncthreads();
        // ---- mma phase (identical fragment pattern to gemm_h) ----
        const uint32_t* Wb = Ws + s * PB_W;
        const uint32_t* Gw = Gs + s * 3456;
#pragma unroll
        for (int kb = 0; kb < 2; kb++) {
            uint32_t af[3][4], bf[8][2];
#pragma unroll
            for (int mf = 0; mf < 3; mf++) {
                int r = wm + mf * 16 + q;
                uint2 lo = *(const uint2*)&Gw[r * 24 + kb * 8 + 2 * cc];
                uint2 hi = *(const uint2*)&Gw[(r + 8) * 24 + kb * 8 + 2 * cc];
                af[mf][0] = lo.x; af[mf][1] = hi.x;
                af[mf][2] = lo.y; af[mf][3] = hi.y;
            }
#pragma unroll
            for (int nf = 0; nf < 8; nf++) {
                int n = wn + nf * 8 + q;
                bf[nf][0] = Wb[(kb * 8 + 2 * cc) * 260 + n];
                bf[nf][1] = Wb[(kb * 8 + 2 * cc + 1) * 260 + n];
            }
#pragma unroll
            for (int mf = 0; mf < 3; mf++)
#pragma unroll
                for (int nf = 0; nf < 8; nf++)
                    mma16(acc[mf][nf], af[mf], bf[nf]);
        }
        __syncthreads();
        if (tid == 0 && kc + 2 < 64) issue(kc + 2);
    }

    // epilogue: partial scores over this 256-col slice (deterministic order)
    const float* b0g = b0 + slice * 256;
    const float* W1g = W1 + slice * 256;
#pragma unroll
    for (int mf = 0; mf < 3; mf++) {
        float s0 = 0.f, s1 = 0.f;
#pragma unroll
        for (int nf = 0; nf < 8; nf++) {
            int c0 = wn + nf * 8 + 2 * cc;
            float w0 = W1g[c0],     e0 = b0g[c0];
            float w1 = W1g[c0 + 1], e1 = b0g[c0 + 1];
            s0 += w0 * tanhf(acc[mf][nf][0] + e0) + w1 * tanhf(acc[mf][nf][1] + e1);
            s1 += w0 * tanhf(acc[mf][nf][2] + e0) + w1 * tanhf(acc[mf][nf][3] + e1);
        }
        s0 += __shfl_xor_sync(0xffffffffu, s0, 1);
        s0 += __shfl_xor_sync(0xffffffffu, s0, 2);
        s1 += __shfl_xor_sync(0xffffffffu, s1, 1);
        s1 += __shfl_xor_sync(0xffffffffu, s1, 2);
        if (cc == 0) {
            int r = wm + mf * 16 + q;
            red[r * 4 + (wid & 3)]       = s0;
            red[(r + 8) * 4 + (wid & 3)] = s1;
        }
    }
    __syncthreads();
    if (tid < 144) {
        float tot = red[tid * 4] + red[tid * 4 + 1] + red[tid * 4 + 2] + red[tid * 4 + 3];
        scp[(((size_t)slice * B_ + b) * 9 + ig) * 144 + tid] = tot;
    }
}

// softmax over j for each (b,i)
__global__ void attk(const float* __restrict__ scp, float* __restrict__ att) {
    int bi = blockIdx.x * blockDim.x + threadIdx.x;
    if (bi >= ROWS) return;
    int b = bi / N_, i = bi - b * N_;
    int ig = i >> 2, il = i & 3;
    float sc[N_];
#pragma unroll 4
    for (int j = 0; j < N_; j++) {
        sc[j] = scp[(((size_t)b) * 9 + ig) * 144 + il * 36 + j]
              + scp[(((size_t)B_ + b) * 9 + ig) * 144 + il * 36 + j];
    }
    float m = sc[0];
    for (int j = 1; j < N_; j++) m = fmaxf(m, sc[j]);
    float sum = 0.f;
    for (int j = 0; j < N_; j++) { sc[j] = expf(sc[j] - m); sum += sc[j]; }
    float inv = 1.f / sum;
    for (int j = 0; j < N_; j++) att[(size_t)bi * N_ + j] = sc[j] * inv;
}

// out = obj + fused + ra.*(att@rb) + ba.*(att@bb)
__global__ __launch_bounds__(256)
void ehat_fin(const float* __restrict__ att,
              const float* __restrict__ ra, const float* __restrict__ rb,
              const float* __restrict__ ba, const float* __restrict__ bb,
              const float* __restrict__ obj, const float* __restrict__ fus,
              float* __restrict__ out) {
    __shared__ float att_s[N_][N_ + 1];
    const int tid = threadIdx.x;
    const int b = blockIdx.y, d0 = blockIdx.x * 128;
    const int d = tid & 127, half = tid >> 7;
    for (int idx = tid; idx < N_ * N_; idx += 256)
        att_s[idx / N_][idx % N_] = att[(size_t)(b * N_ + idx / N_) * N_ + idx % N_];
    __syncthreads();
    const float* rbB = rb + (size_t)b * N_ * DF + d0 + d;
    const float* bbB = bb + (size_t)b * N_ * DF + d0 + d;
    float accR[18], accB[18];
#pragma unroll
    for (int i = 0; i < 18; i++) { accR[i] = 0.f; accB[i] = 0.f; }
    for (int j = 0; j < N_; j++) {
        float rv = rbB[(size_t)j * DF];
        float bv = bbB[(size_t)j * DF];
#pragma unroll
        for (int i = 0; i < 18; i++) {
            float a = att_s[half * 18 + i][j];
            accR[i] += a * rv;
            accB[i] += a * bv;
        }
    }
#pragma unroll
    for (int i = 0; i < 18; i++) {
        size_t row = (size_t)b * N_ + half * 18 + i;
        size_t off = row * DF + d0 + d;
        out[off] = obj[off] + fus[off] + ra[off] * accR[i] + ba[off] * accB[i];
    }
}

extern "C" void kernel_launch(void* const* d_in, const int* in_sizes, int n_in,
                              void* d_out, int out_size) {
    const float* qe    = (const float*)d_in[0];
    const float* obj   = (const float*)d_in[1];
    const float* boxes = (const float*)d_in[2];
    const float* Wq    = (const float*)d_in[3];
    const float* Wo    = (const float*)d_in[4];
    const float* Wfa   = (const float*)d_in[5];
    const float* Wfb   = (const float*)d_in[6];
    const float* Wba   = (const float*)d_in[7];
    const float* Wbb   = (const float*)d_in[8];
    const float* W0    = (const float*)d_in[9];
    const float* b0    = (const float*)d_in[10];
    const float* W1    = (const float*)d_in[11];
    float* out = (float*)d_out;

    float *tmp1, *tmp2, *ra, *rb, *ba, *bb;
    float *pra, *prb, *pba, *pbb, *scp, *attb;
    uint32_t *pqe, *pobj, *pfus, *pWq, *pWo, *pWfa, *pWfb, *pW0h;
    cudaGetSymbolAddress((void**)&tmp1, g_tmp1);
    cudaGetSymbolAddress((void**)&tmp2, g_tmp2);
    cudaGetSymbolAddress((void**)&ra,   g_ra);
    cudaGetSymbolAddress((void**)&rb,   g_rb);
    cudaGetSymbolAddress((void**)&ba,   g_ba);
    cudaGetSymbolAddress((void**)&bb,   g_bb);
    cudaGetSymbolAddress((void**)&pqe,  g_pqe);
    cudaGetSymbolAddress((void**)&pobj, g_pobj);
    cudaGetSymbolAddress((void**)&pfus, g_pfus);
    cudaGetSymbolAddress((void**)&pWq,  g_pWq);
    cudaGetSymbolAddress((void**)&pWo,  g_pWo);
    cudaGetSymbolAddress((void**)&pWfa, g_pWfa);
    cudaGetSymbolAddress((void**)&pWfb, g_pWfb);
    cudaGetSymbolAddress((void**)&pW0h, g_pW0h);
    cudaGetSymbolAddress((void**)&pra,  g_pra);
    cudaGetSymbolAddress((void**)&prb,  g_prb);
    cudaGetSymbolAddress((void**)&pba,  g_pba);
    cudaGetSymbolAddress((void**)&pbb,  g_pbb);
    cudaGetSymbolAddress((void**)&scp,  g_scp);
    cudaGetSymbolAddress((void**)&attb, g_attb);

    cudaFuncSetAttribute(gemm_h, cudaFuncAttributeMaxDynamicSharedMemorySize, G_SMEM);
    cudaFuncSetAttribute(relattn_h2, cudaFuncAttributeMaxDynamicSharedMemorySize, R_SMEM);

    const int nIO  = ROWS * DF / 4;          // 1179648
    const int nWp  = (DF / 2) * (DF / 4);    // 524288
    const int nW0p = (DF / 2) * (DATT / 4);  // 131072

    dim3 gg(DF / 256, ROWS / 128);           // (8, 18)

    packWh<<<(nWp + 255) / 256, 256>>>(Wq,  pWq,  DF);
    packAh<<<(nIO + 255) / 256, 256>>>(qe,  pqe);
    packWh<<<(nWp + 255) / 256, 256>>>(Wo,  pWo,  DF);
    packAh<<<(nIO + 255) / 256, 256>>>(obj, pobj);
    packWh<<<(nWp + 255) / 256, 256>>>(Wfa, pWfa, DF);
    gemm_h<<<gg, 256, G_SMEM>>>(pqe,  pWq, tmp1, nullptr);   // 6th launch
    packWh<<<(nWp + 255) / 256, 256>>>(Wfb, pWfb, DF);
    packWh<<<(nW0p + 255) / 256, 256>>>(W0, pW0h, DATT);
    gemm_h<<<gg, 256, G_SMEM>>>(pobj, pWo, tmp2, nullptr);
    fusekh<<<(nIO + 255) / 256, 256>>>(tmp1, tmp2, pfus);
    gemm_h<<<gg, 256, G_SMEM>>>(pfus, pWfa, ra, pra);
    gemm_h<<<gg, 256, G_SMEM>>>(pfus, pWfb, rb, prb);
    boxproj<<<(nIO + 255) / 256, 256>>>(boxes, Wba, Wbb, ba, bb, pba, pbb);

    relattn_h2<<<dim3(2, 9, B_), 384, R_SMEM>>>(pra, prb, pba, pbb, pW0h, b0, W1, scp);
    attk<<<(ROWS + 127) / 128, 128>>>(scp, attb);
    ehat_fin<<<dim3(16, B_), 256>>>(attb, ra, rb, ba, bb, obj, tmp1, out);
}

// round 15
// speedup vs baseline: 1.8944x; 1.0685x over previous
#include <cuda_runtime.h>
#include <cuda_fp16.h>
#include <math.h>
#include <stdint.h>

#define B_   64
#define N_   36
#define ROWS 2304      // B_*N_
#define DF   2048
#define DATT 512

// packed chunk sizes
#define PA_W 3072      // fp16 A: 128 rows x 24 words
#define PB_W 4160      // fp16 W: 16 word-rows x 260
#define PR_CH 1440     // fp32 relattn operands: 36 x 40 floats

// ---------------- scratch ----------------------------------------------------
__device__ float    g_tmp1[ROWS * DF];     // qe@Wq, then unrounded fused
__device__ float    g_tmp2[ROWS * DF];     // obj@Wo
__device__ float    g_ra[ROWS * DF];       // natural outputs
__device__ float    g_rb[ROWS * DF];
__device__ float    g_ba[ROWS * DF];
__device__ float    g_bb[ROWS * DF];
__device__ uint32_t g_pqe[18 * 64 * PA_W];    // packed fp16 A operands
__device__ uint32_t g_pobj[18 * 64 * PA_W];
__device__ uint32_t g_pfus[18 * 64 * PA_W];
__device__ uint32_t g_pWq[8 * 64 * PB_W];     // packed fp16 weights
__device__ uint32_t g_pWo[8 * 64 * PB_W];
__device__ uint32_t g_pWfa[8 * 64 * PB_W];
__device__ uint32_t g_pWfb[8 * 64 * PB_W];
__device__ uint32_t g_pW0h[2 * 64 * PB_W];    // packed fp16 W0 (relattn)
__device__ float    g_pra[B_ * 64 * PR_CH];   // packed raw fp32 relattn operands
__device__ float    g_prb[B_ * 64 * PR_CH];
__device__ float    g_pba[B_ * 64 * PR_CH];
__device__ float    g_pbb[B_ * 64 * PR_CH];
__device__ float    g_scp[2 * 9 * B_ * 144];

// ---------------- PTX helpers ------------------------------------------------
__device__ __forceinline__ uint32_t smem_u32(const void* p) {
    uint32_t a;
    asm("{ .reg .u64 t; cvta.to.shared.u64 t, %1; cvt.u32.u64 %0, t; }" : "=r"(a) : "l"(p));
    return a;
}
__device__ __forceinline__ uint32_t packh2(float x, float y) {
    __half2 h = __floats2half2_rn(x, y);
    return *(uint32_t*)&h;
}
__device__ __forceinline__ void mma16(float* d, const uint32_t* a, const uint32_t* b) {
    asm volatile("mma.sync.aligned.m16n8k16.row.col.f32.f16.f16.f32 "
                 "{%0,%1,%2,%3}, {%4,%5,%6,%7}, {%8,%9}, {%0,%1,%2,%3};"
                 : "+f"(d[0]), "+f"(d[1]), "+f"(d[2]), "+f"(d[3])
                 : "r"(a[0]), "r"(a[1]), "r"(a[2]), "r"(a[3]),
                   "r"(b[0]), "r"(b[1]));
}
__device__ __forceinline__ void blkcp(uint32_t dst, const void* src,
                                      uint32_t bytes, uint32_t bar) {
    asm volatile("cp.async.bulk.shared::cta.global.mbarrier::complete_tx::bytes "
                 "[%0], [%1], %2, [%3];"
                 :: "r"(dst), "l"(src), "r"(bytes), "r"(bar) : "memory");
}
#define MBAR_INIT(a, n) \
    asm volatile("mbarrier.init.shared.b64 [%0], %1;" :: "r"(a), "r"(n) : "memory")
#define MBAR_EXPECT(a, n) \
    asm volatile("mbarrier.arrive.expect_tx.shared.b64 _, [%0], %1;" :: "r"(a), "r"(n) : "memory")
#define MBAR_WAIT(a, ph) do {                                                   \
    uint32_t _m = (a), _p = (ph), _d;                                           \
    asm volatile("{\n\t.reg .pred p;\n\t"                                       \
        "mbarrier.try_wait.parity.acquire.cta.shared::cta.b64 p, [%1], %2;\n\t" \
        "selp.b32 %0, 1, 0, p;\n\t}" : "=r"(_d) : "r"(_m), "r"(_p) : "memory"); \
    if (!_d) {                                                                  \
        asm volatile("{\n\t.reg .pred P;\n\t"                                   \
            "WL_%=:\n\t"                                                        \
            "mbarrier.try_wait.parity.acquire.cta.shared::cta.b64 P, [%0], %1, 0x989680;\n\t" \
            "@P bra.uni WD_%=;\n\t"                                             \
            "bra.uni WL_%=;\n\t"                                                \
            "WD_%=:\n\t}" :: "r"(_m), "r"(_p) : "memory");                      \
    } } while (0)

// k-word permutation within a K=16 block (8 half2 words):
// logical w -> phys (w<4 ? 2w : 2(w-4)+1): fragment pairs adjacent -> LDS.64
__device__ __forceinline__ int kperm(int wl) {
    int blk = wl >> 3, wi = wl & 7;
    return blk * 8 + ((wi < 4) ? 2 * wi : 2 * (wi - 4) + 1);
}

// ---------------- packing / elementwise kernels ------------------------------
// All 5 weight packs in one launch. z<4: [2048][2048]; z=4: W0 [2048][512].
__global__ void packWall(const float* __restrict__ Wq, const float* __restrict__ Wo,
                         const float* __restrict__ Wfa, const float* __restrict__ Wfb,
                         const float* __restrict__ W0,
                         uint32_t* __restrict__ pWq, uint32_t* __restrict__ pWo,
                         uint32_t* __restrict__ pWfa, uint32_t* __restrict__ pWfb,
                         uint32_t* __restrict__ pW0h) {
    int z = blockIdx.z;
    const float* in;
    uint32_t* out;
    int ncols;
    switch (z) {
        case 0: in = Wq;  out = pWq;  ncols = DF;   break;
        case 1: in = Wo;  out = pWo;  ncols = DF;   break;
        case 2: in = Wfa; out = pWfa; ncols = DF;   break;
        case 3: in = Wfb; out = pWfb; ncols = DF;   break;
        default: in = W0; out = pW0h; ncols = DATT; break;
    }
    int i = blockIdx.x * blockDim.x + threadIdx.x;
    int nq = ncols / 4;
    if (i >= (DF / 2) * nq) return;
    int n4 = (i % nq) * 4;
    int kk = (i / nq) * 2;
    float4 a = *(const float4*)&in[(size_t)kk * ncols + n4];
    float4 b = *(const float4*)&in[(size_t)(kk + 1) * ncols + n4];
    uint4 w;
    w.x = packh2(a.x, b.x); w.y = packh2(a.y, b.y);
    w.z = packh2(a.z, b.z); w.w = packh2(a.w, b.w);
    int p = kperm((kk & 31) >> 1);
    size_t o = ((size_t)((n4 >> 8) * 64 + (kk >> 5)) * 16 + p) * 260 + (n4 & 255);
    *(uint4*)&out[o] = w;
}

// A packs (qe, obj) in one launch: grid (4608, 1, 2)
__global__ void packAh2(const float* __restrict__ qe, const float* __restrict__ obj,
                        uint32_t* __restrict__ pqe, uint32_t* __restrict__ pobj) {
    const float* in  = blockIdx.z ? obj : qe;
    uint32_t* out    = blockIdx.z ? pobj : pqe;
    int i = blockIdx.x * blockDim.x + threadIdx.x;
    if (i >= ROWS * DF / 4) return;
    int e = i * 4;
    int r = e / DF, c = e % DF;
    float4 v = *(const float4*)&in[e];
    uint32_t h0 = packh2(v.x, v.y), h1 = packh2(v.z, v.w);
    size_t rowb = ((size_t)((r >> 7) * 64 + (c >> 5)) * 128 + (r & 127)) * 24;
    int wl = (c & 31) >> 1;
    out[rowb + kperm(wl)]     = h0;
    out[rowb + kperm(wl + 1)] = h1;
}

// tmp1 = tmp1*tmp2 (natural fp32, residual); packed fp16 product -> pfus
__global__ void fusekh(float* __restrict__ a, const float* __restrict__ b,
                       uint32_t* __restrict__ pk) {
    int i = blockIdx.x * blockDim.x + threadIdx.x;
    if (i >= ROWS * DF / 4) return;
    int e = i * 4;
    int r = e / DF, c = e % DF;
    float4 x = *(float4*)&a[e];
    float4 y = *(const float4*)&b[e];
    x.x *= y.x; x.y *= y.y; x.z *= y.z; x.w *= y.w;
    *(float4*)&a[e] = x;
    uint32_t h0 = packh2(x.x, x.y), h1 = packh2(x.z, x.w);
    size_t rowb = ((size_t)((r >> 7) * 64 + (c >> 5)) * 128 + (r & 127)) * 24;
    int wl = (c & 31) >> 1;
    pk[rowb + kperm(wl)]     = h0;
    pk[rowb + kperm(wl + 1)] = h1;
}

// ba/bb natural + packed relattn layout, from boxes (K = 4)
__global__ void boxproj(const float* __restrict__ boxes,
                        const float* __restrict__ Wba, const float* __restrict__ Wbb,
                        float* __restrict__ ba, float* __restrict__ bb,
                        float* __restrict__ pba, float* __restrict__ pbb) {
    int idx = blockIdx.x * blockDim.x + threadIdx.x;
    if (idx >= ROWS * (DF / 4)) return;
    int r  = idx / (DF / 4);
    int dq = (idx % (DF / 4)) * 4;
    float4 bx = *(const float4*)&boxes[r * 4];
    float c[4] = {bx.x, bx.y, bx.z, bx.w};
    float4 sa = make_float4(0.f, 0.f, 0.f, 0.f);
    float4 sb = make_float4(0.f, 0.f, 0.f, 0.f);
#pragma unroll
    for (int cc = 0; cc < 4; cc++) {
        float4 wa = *(const float4*)&Wba[cc * DF + dq];
        float4 wb = *(const float4*)&Wbb[cc * DF + dq];
        sa.x += c[cc] * wa.x; sa.y += c[cc] * wa.y; sa.z += c[cc] * wa.z; sa.w += c[cc] * wa.w;
        sb.x += c[cc] * wb.x; sb.y += c[cc] * wb.y; sb.z += c[cc] * wb.z; sb.w += c[cc] * wb.w;
    }
    *(float4*)&ba[(size_t)r * DF + dq] = sa;
    *(float4*)&bb[(size_t)r * DF + dq] = sb;
    int b = r / N_, j = r - b * N_;
    size_t o = ((size_t)(b * 64 + (dq >> 5)) * 36 + j) * 40 + (dq & 31);
    *(float4*)&pba[o] = sa;
    *(float4*)&pbb[o] = sb;
}

// ---------------------------------------------------------------------------
// Dual fp16 mma.sync GEMM (fp32 acc): grid (8, 18, 2), z selects operand set.
// CTA 128x256, 3 stages, K-chunk 32 (2 x K16), 8 warps of 64x64.
// (issue comes AFTER the sync that follows mma -> no buffer race.)
// ---------------------------------------------------------------------------
#define G_SMEM ((16 + 3 * PA_W + 3 * PB_W) * 4)
__global__ __launch_bounds__(256)
void gemm_hz(const uint32_t* __restrict__ pa0, const uint32_t* __restrict__ pb0,
             float* __restrict__ C0, float* __restrict__ Cp0,
             const uint32_t* __restrict__ pa1, const uint32_t* __restrict__ pb1,
             float* __restrict__ C1, float* __restrict__ Cp1) {
    const uint32_t* pa = blockIdx.z ? pa1 : pa0;
    const uint32_t* pb = blockIdx.z ? pb1 : pb0;
    float* C  = blockIdx.z ? C1 : C0;
    float* Cp = blockIdx.z ? Cp1 : Cp0;

    extern __shared__ uint32_t smw[];
    uint32_t smb = smem_u32(smw);
    const int tid = threadIdx.x, lane = tid & 31, wid = tid >> 5;
    const int cc = lane & 3, q = lane >> 2;
    const int wm = (wid >> 2) * 64, wn = (wid & 3) * 64;
    const int tileM = blockIdx.y, tileN = blockIdx.x;
    const uint32_t* As = smw + 16;
    const uint32_t* Bs = smw + 16 + 3 * PA_W;

    if (tid == 0) {
#pragma unroll
        for (int s = 0; s < 3; s++) MBAR_INIT(smb + 8 * s, 1);
    }
    __syncthreads();

    auto issue = [&](int kc) {
        int s = kc % 3;
        uint32_t bar = smb + 8 * s;
        MBAR_EXPECT(bar, 28928);
        blkcp(smb + (16 + s * PA_W) * 4,
              pa + ((size_t)tileM * 64 + kc) * PA_W, 12288, bar);
        blkcp(smb + (16 + 3 * PA_W + s * PB_W) * 4,
              pb + ((size_t)tileN * 64 + kc) * PB_W, 16640, bar);
    };
    if (tid == 0) { issue(0); issue(1); issue(2); }

    float acc[4][8][4];
#pragma unroll
    for (int i = 0; i < 4; i++)
#pragma unroll
        for (int j = 0; j < 8; j++)
#pragma unroll
            for (int p = 0; p < 4; p++) acc[i][j][p] = 0.f;

    for (int kc = 0; kc < 64; kc++) {
        int s = kc % 3;
        MBAR_WAIT(smb + 8 * s, (kc / 3) & 1);
        const uint32_t* Ab = As + s * PA_W;
        const uint32_t* Bb = Bs + s * PB_W;
#pragma unroll
        for (int kb = 0; kb < 2; kb++) {
            uint32_t af[4][4], bf[8][2];
#pragma unroll
            for (int mf = 0; mf < 4; mf++) {
                int r = wm + mf * 16 + q;
                uint2 lo = *(const uint2*)&Ab[r * 24 + kb * 8 + 2 * cc];
                uint2 hi = *(const uint2*)&Ab[(r + 8) * 24 + kb * 8 + 2 * cc];
                af[mf][0] = lo.x; af[mf][1] = hi.x;
                af[mf][2] = lo.y; af[mf][3] = hi.y;
            }
#pragma unroll
            for (int nf = 0; nf < 8; nf++) {
                int n = wn + nf * 8 + q;
                bf[nf][0] = Bb[(kb * 8 + 2 * cc) * 260 + n];
                bf[nf][1] = Bb[(kb * 8 + 2 * cc + 1) * 260 + n];
            }
#pragma unroll
            for (int mf = 0; mf < 4; mf++)
#pragma unroll
                for (int nf = 0; nf < 8; nf++)
                    mma16(acc[mf][nf], af[mf], bf[nf]);
        }
        __syncthreads();
        if (tid == 0 && kc + 3 < 64) issue(kc + 3);
    }

    const int m0 = tileM * 128, n0 = tileN * 256;
#pragma unroll
    for (int mf = 0; mf < 4; mf++) {
        int r0 = m0 + wm + mf * 16 + q;
#pragma unroll
        for (int nf = 0; nf < 8; nf++) {
            int c = n0 + wn + nf * 8 + 2 * cc;
            float2 v0 = make_float2(acc[mf][nf][0], acc[mf][nf][1]);
            float2 v1 = make_float2(acc[mf][nf][2], acc[mf][nf][3]);
            *(float2*)&C[(size_t)r0 * DF + c] = v0;
            *(float2*)&C[(size_t)(r0 + 8) * DF + c] = v1;
            if (Cp) {
                int b0i = r0 / 36, j0 = r0 - b0i * 36;
                int b1i = (r0 + 8) / 36, j1 = (r0 + 8) - b1i * 36;
                size_t o0 = ((size_t)(b0i * 64 + (c >> 5)) * 36 + j0) * 40 + (c & 31);
                size_t o1 = ((size_t)(b1i * 64 + (c >> 5)) * 36 + j1) * 40 + (c & 31);
                *(float2*)&Cp[o0] = v0;
                *(float2*)&Cp[o1] = v1;
            }
        }
    }
}

// ---------------------------------------------------------------------------
// Relation-attention scores, fp16 mma + smem G-build, single sync per chunk,
// THREE-stage operand buffers (race fix vs round 13):
// at iter kc, free slot = (kc-1)%3 = (kc+2)%3 -> issue(kc+2) is safe.
//   prologue: issue 0,1,2; wait(0); buildG(0)
//   loop kc:  sync; [kc>=1] issue(kc+2); mma(G[kc] w/ Ws[kc%3]);
//             wait((kc+1)%3); buildG(kc+1)
// smem words: bars 0..15, Ws@16 (3x4160), rbS@12496 (3x1440), bbS@16816,
//   raS@21136 (3x160), baS@21616, Gs@22096 (2x3456), red@29008. 29584 words.
// ---------------------------------------------------------------------------
#define R_SMEM (29584 * 4)
__global__ __launch_bounds__(384)
void relattn_h4(const float* __restrict__ pra, const float* __restrict__ prb,
                const float* __restrict__ pba, const float* __restrict__ pbb,
                const uint32_t* __restrict__ pw0, const float* __restrict__ b0,
                const float* __restrict__ W1, float* __restrict__ scp) {
    extern __shared__ uint32_t smw[];
    float* smf = (float*)smw;
    uint32_t smb = smem_u32(smw);
    const uint32_t* Ws = smw + 16;
    const float* rbS = smf + 12496;
    const float* bbS = smf + 16816;
    const float* raS = smf + 21136;
    const float* baS = smf + 21616;
    uint32_t* Gs = smw + 22096;
    float* red = smf + 29008;
    const int tid = threadIdx.x, lane = tid & 31, wid = tid >> 5;
    const int cc = lane & 3, q = lane >> 2;
    const int wm = (wid >> 2) * 48, wn = (wid & 3) * 64;
    const int slice = blockIdx.x, ig = blockIdx.y, b = blockIdx.z;

    if (tid == 0) {
#pragma unroll
        for (int s = 0; s < 3; s++) MBAR_INIT(smb + 8 * s, 1);
    }
    __syncthreads();

    auto issue = [&](int kc) {
        int s = kc % 3;
        uint32_t bar = smb + 8 * s;
        MBAR_EXPECT(bar, 29440);
        blkcp(smb + (16 + s * PB_W) * 4,
              pw0 + ((size_t)slice * 64 + kc) * PB_W, 16640, bar);
        size_t rbase = ((size_t)b * 64 + kc) * PR_CH;
        blkcp(smb + (12496 + s * PR_CH) * 4, prb + rbase, 5760, bar);
        blkcp(smb + (16816 + s * PR_CH) * 4, pbb + rbase, 5760, bar);
        blkcp(smb + (21136 + s * 160) * 4, pra + rbase + ig * 160, 640, bar);
        blkcp(smb + (21616 + s * 160) * 4, pba + rbase + ig * 160, 640, bar);
    };
    auto buildG = [&](int kc) {
        int s = kc % 3;
        const float* rs = rbS + s * PR_CH;
        const float* bs = bbS + s * PR_CH;
        const float* us = raS + s * 160;
        const float* vs = baS + s * 160;
        uint32_t* Gw = Gs + (kc & 1) * 3456;
#pragma unroll
        for (int p = 0; p < 6; p++) {
            int idx = tid + 384 * p;       // < 2304
            int r = idx >> 4, wl = idx & 15;
            int il = r / 36, j = r - il * 36;
            int k = 2 * wl;
            float2 rv = *(const float2*)&rs[j * 40 + k];
            float2 bv = *(const float2*)&bs[j * 40 + k];
            float2 u  = *(const float2*)&us[il * 40 + k];
            float2 v  = *(const float2*)&vs[il * 40 + k];
            float g0 = fmaf(v.x, bv.x, u.x * rv.x);
            float g1 = fmaf(v.y, bv.y, u.y * rv.y);
            Gw[r * 24 + kperm(wl)] = packh2(g0, g1);
        }
    };

    if (tid == 0) { issue(0); issue(1); issue(2); }

    float acc[3][8][4];
#pragma unroll
    for (int i = 0; i < 3; i++)
#pragma unroll
        for (int j = 0; j < 8; j++)
#pragma unroll
            for (int p = 0; p < 4; p++) acc[i][j][p] = 0.f;

    MBAR_WAIT(smb + 0, 0);
    buildG(0);

    for (int kc = 0; kc < 64; kc++) {
        int s = kc % 3;
        __syncthreads();   // G[kc] visible; mma reads of slot (kc-1)%3 all done
        if (tid == 0 && kc >= 1 && kc + 2 < 64) issue(kc + 2);
        // mma phase on G[kc] vs Ws[kc%3]
        const uint32_t* Wb = Ws + s * PB_W;
        const uint32_t* Gw = Gs + (kc & 1) * 3456;
#pragma unroll
        for (int kb = 0; kb < 2; kb++) {
            uint32_t af[3][4], bf[8][2];
#pragma unroll
            for (int mf = 0; mf < 3; mf++) {
                int r = wm + mf * 16 + q;
                uint2 lo = *(const uint2*)&Gw[r * 24 + kb * 8 + 2 * cc];
                uint2 hi = *(const uint2*)&Gw[(r + 8) * 24 + kb * 8 + 2 * cc];
                af[mf][0] = lo.x; af[mf][1] = hi.x;
                af[mf][2] = lo.y; af[mf][3] = hi.y;
            }
#pragma unroll
            for (int nf = 0; nf < 8; nf++) {
                int n = wn + nf * 8 + q;
                bf[nf][0] = Wb[(kb * 8 + 2 * cc) * 260 + n];
                bf[nf][1] = Wb[(kb * 8 + 2 * cc + 1) * 260 + n];
            }
#pragma unroll
            for (int mf = 0; mf < 3; mf++)
#pragma unroll
                for (int nf = 0; nf < 8; nf++)
                    mma16(acc[mf][nf], af[mf], bf[nf]);
        }
        // overlap: wait + build next chunk's G while mma drains
        if (kc + 1 < 64) {
            MBAR_WAIT(smb + 8 * ((kc + 1) % 3), ((kc + 1) / 3) & 1);
            buildG(kc + 1);
        }
    }
    __syncthreads();

    // epilogue: partial scores over this 256-col slice (deterministic order)
    const float* b0g = b0 + slice * 256;
    const float* W1g = W1 + slice * 256;
#pragma unroll
    for (int mf = 0; mf < 3; mf++) {
        float s0 = 0.f, s1 = 0.f;
#pragma unroll
        for (int nf = 0; nf < 8; nf++) {
            int c0 = wn + nf * 8 + 2 * cc;
            float w0 = W1g[c0],     e0 = b0g[c0];
            float w1 = W1g[c0 + 1], e1 = b0g[c0 + 1];
            s0 += w0 * tanhf(acc[mf][nf][0] + e0) + w1 * tanhf(acc[mf][nf][1] + e1);
            s1 += w0 * tanhf(acc[mf][nf][2] + e0) + w1 * tanhf(acc[mf][nf][3] + e1);
        }
        s0 += __shfl_xor_sync(0xffffffffu, s0, 1);
        s0 += __shfl_xor_sync(0xffffffffu, s0, 2);
        s1 += __shfl_xor_sync(0xffffffffu, s1, 1);
        s1 += __shfl_xor_sync(0xffffffffu, s1, 2);
        if (cc == 0) {
            int r = wm + mf * 16 + q;
            red[r * 4 + (wid & 3)]       = s0;
            red[(r + 8) * 4 + (wid & 3)] = s1;
        }
    }
    __syncthreads();
    if (tid < 144) {
        float tot = red[tid * 4] + red[tid * 4 + 1] + red[tid * 4 + 2] + red[tid * 4 + 3];
        scp[(((size_t)slice * B_ + b) * 9 + ig) * 144 + tid] = tot;
    }
}

// out = obj + fused + ra.*(att@rb) + ba.*(att@bb); softmax computed in-block.
__global__ __launch_bounds__(256)
void ehat_fin2(const float* __restrict__ scp,
               const float* __restrict__ ra, const float* __restrict__ rb,
               const float* __restrict__ ba, const float* __restrict__ bb,
               const float* __restrict__ obj, const float* __restrict__ fus,
               float* __restrict__ out) {
    __shared__ float att_s[N_][N_ + 1];
    const int tid = threadIdx.x;
    const int b = blockIdx.y, d0 = blockIdx.x * 128;
    const int d = tid & 127, half = tid >> 7;
    for (int idx = tid; idx < N_ * N_; idx += 256) {
        int i = idx / N_, j = idx % N_;
        int ig = i >> 2, il = i & 3;
        float s = scp[(((size_t)b) * 9 + ig) * 144 + il * 36 + j]
                + scp[(((size_t)B_ + b) * 9 + ig) * 144 + il * 36 + j];
        att_s[i][j] = s;
    }
    __syncthreads();
    if (tid < N_) {       // per-i softmax, serial = deterministic
        float m = att_s[tid][0];
#pragma unroll 4
        for (int j = 1; j < N_; j++) m = fmaxf(m, att_s[tid][j]);
        float sum = 0.f;
#pragma unroll 4
        for (int j = 0; j < N_; j++) {
            float e = expf(att_s[tid][j] - m);
            att_s[tid][j] = e;
            sum += e;
        }
        float inv = 1.f / sum;
#pragma unroll 4
        for (int j = 0; j < N_; j++) att_s[tid][j] *= inv;
    }
    __syncthreads();
    const float* rbB = rb + (size_t)b * N_ * DF + d0 + d;
    const float* bbB = bb + (size_t)b * N_ * DF + d0 + d;
    float accR[18], accB[18];
#pragma unroll
    for (int i = 0; i < 18; i++) { accR[i] = 0.f; accB[i] = 0.f; }
    for (int j = 0; j < N_; j++) {
        float rv = rbB[(size_t)j * DF];
        float bv = bbB[(size_t)j * DF];
#pragma unroll
        for (int i = 0; i < 18; i++) {
            float a = att_s[half * 18 + i][j];
            accR[i] += a * rv;
            accB[i] += a * bv;
        }
    }
#pragma unroll
    for (int i = 0; i < 18; i++) {
        size_t row = (size_t)b * N_ + half * 18 + i;
        size_t off = row * DF + d0 + d;
        out[off] = obj[off] + fus[off] + ra[off] * accR[i] + ba[off] * accB[i];
    }
}

extern "C" void kernel_launch(void* const* d_in, const int* in_sizes, int n_in,
                              void* d_out, int out_size) {
    const float* qe    = (const float*)d_in[0];
    const float* obj   = (const float*)d_in[1];
    const float* boxes = (const float*)d_in[2];
    const float* Wq    = (const float*)d_in[3];
    const float* Wo    = (const float*)d_in[4];
    const float* Wfa   = (const float*)d_in[5];
    const float* Wfb   = (const float*)d_in[6];
    const float* Wba   = (const float*)d_in[7];
    const float* Wbb   = (const float*)d_in[8];
    const float* W0    = (const float*)d_in[9];
    const float* b0    = (const float*)d_in[10];
    const float* W1    = (const float*)d_in[11];
    float* out = (float*)d_out;

    float *tmp1, *tmp2, *ra, *rb, *ba, *bb;
    float *pra, *prb, *pba, *pbb, *scp;
    uint32_t *pqe, *pobj, *pfus, *pWq, *pWo, *pWfa, *pWfb, *pW0h;
    cudaGetSymbolAddress((void**)&tmp1, g_tmp1);
    cudaGetSymbolAddress((void**)&tmp2, g_tmp2);
    cudaGetSymbolAddress((void**)&ra,   g_ra);
    cudaGetSymbolAddress((void**)&rb,   g_rb);
    cudaGetSymbolAddress((void**)&ba,   g_ba);
    cudaGetSymbolAddress((void**)&bb,   g_bb);
    cudaGetSymbolAddress((void**)&pqe,  g_pqe);
    cudaGetSymbolAddress((void**)&pobj, g_pobj);
    cudaGetSymbolAddress((void**)&pfus, g_pfus);
    cudaGetSymbolAddress((void**)&pWq,  g_pWq);
    cudaGetSymbolAddress((void**)&pWo,  g_pWo);
    cudaGetSymbolAddress((void**)&pWfa, g_pWfa);
    cudaGetSymbolAddress((void**)&pWfb, g_pWfb);
    cudaGetSymbolAddress((void**)&pW0h, g_pW0h);
    cudaGetSymbolAddress((void**)&pra,  g_pra);
    cudaGetSymbolAddress((void**)&prb,  g_prb);
    cudaGetSymbolAddress((void**)&pba,  g_pba);
    cudaGetSymbolAddress((void**)&pbb,  g_pbb);
    cudaGetSymbolAddress((void**)&scp,  g_scp);

    cudaFuncSetAttribute(gemm_hz, cudaFuncAttributeMaxDynamicSharedMemorySize, G_SMEM);
    cudaFuncSetAttribute(relattn_h4, cudaFuncAttributeMaxDynamicSharedMemorySize, R_SMEM);

    const int nIO = ROWS * DF / 4;           // 1179648

    dim3 gg(DF / 256, ROWS / 128, 2);        // (8, 18, 2)

    boxproj<<<(nIO + 255) / 256, 256>>>(boxes, Wba, Wbb, ba, bb, pba, pbb);   // 1
    packWall<<<dim3(2048, 1, 5), 256>>>(Wq, Wo, Wfa, Wfb, W0,
                                        pWq, pWo, pWfa, pWfb, pW0h);          // 2
    packAh2<<<dim3(4608, 1, 2), 256>>>(qe, obj, pqe, pobj);                   // 3
    gemm_hz<<<gg, 256, G_SMEM>>>(pqe, pWq, tmp1, nullptr,
                                 pobj, pWo, tmp2, nullptr);                   // 4
    fusekh<<<(nIO + 255) / 256, 256>>>(tmp1, tmp2, pfus);                     // 5
    gemm_hz<<<gg, 256, G_SMEM>>>(pfus, pWfa, ra, pra,
                                 pfus, pWfb, rb, prb);                        // 6 (profiled)
    relattn_h4<<<dim3(2, 9, B_), 384, R_SMEM>>>(pra, prb, pba, pbb,
                                                pW0h, b0, W1, scp);           // 7
    ehat_fin2<<<dim3(16, B_), 256>>>(scp, ra, rb, ba, bb, obj, tmp1, out);    // 8
}